// round 1
// baseline (speedup 1.0000x reference)
#include <cuda_runtime.h>
#include <math.h>

#define Bq   128
#define Sq   512
#define Dq   768
#define NHq  8
#define HDq  96
#define HIDq 384
#define Cq   768            // NH*HD
#define Mq   (Bq*Sq)        // 65536 tokens

// Scratch (allocation rules forbid cudaMalloc; __device__ globals are allowed)
__device__ float g_Hi[(size_t)Mq * Cq];   // 192 MB: per-head projections, [token][c]
__device__ float g_Al[(size_t)Mq * Cq];   // 192 MB: attention logits,      [token][c]

// ---------------------------------------------------------------------------
// K1: Hi[token][c] = sum_d X[token][d] * P[c][d] + bP[c]
// Classic SGEMM: BM=BN=64, BK=16, 256 threads, 4x4 microtile.
// ---------------------------------------------------------------------------
__global__ __launch_bounds__(256) void k1_proj(
    const float* __restrict__ X, const float* __restrict__ P,
    const float* __restrict__ bP)
{
    __shared__ float As[16][68];   // [k][m], padded row to 68 (16B-aligned, low conflict)
    __shared__ float Bs[16][68];   // [k][n]

    const int bm = blockIdx.x * 64;
    const int bn = blockIdx.y * 64;
    const int tid = threadIdx.x;
    const int r  = tid >> 2;             // 0..63
    const int c4 = (tid & 3) << 2;       // 0,4,8,12
    const int tx = tid & 15;             // col group
    const int ty = tid >> 4;             // row group

    float acc[4][4];
    #pragma unroll
    for (int i = 0; i < 4; i++)
        #pragma unroll
        for (int j = 0; j < 4; j++) acc[i][j] = 0.f;

    for (int k0 = 0; k0 < Dq; k0 += 16) {
        float4 a = *reinterpret_cast<const float4*>(&X[(size_t)(bm + r) * Dq + k0 + c4]);
        float4 b = *reinterpret_cast<const float4*>(&P[(size_t)(bn + r) * Dq + k0 + c4]);
        As[c4+0][r] = a.x; As[c4+1][r] = a.y; As[c4+2][r] = a.z; As[c4+3][r] = a.w;
        Bs[c4+0][r] = b.x; Bs[c4+1][r] = b.y; Bs[c4+2][r] = b.z; Bs[c4+3][r] = b.w;
        __syncthreads();
        #pragma unroll
        for (int kk = 0; kk < 16; kk++) {
            float av[4], bv[4];
            #pragma unroll
            for (int i = 0; i < 4; i++) av[i] = As[kk][ty*4 + i];
            #pragma unroll
            for (int j = 0; j < 4; j++) bv[j] = Bs[kk][tx*4 + j];
            #pragma unroll
            for (int i = 0; i < 4; i++)
                #pragma unroll
                for (int j = 0; j < 4; j++)
                    acc[i][j] = fmaf(av[i], bv[j], acc[i][j]);
        }
        __syncthreads();
    }

    float4 bias = *reinterpret_cast<const float4*>(&bP[bn + tx*4]);
    #pragma unroll
    for (int i = 0; i < 4; i++) {
        float4 o;
        o.x = acc[i][0] + bias.x;
        o.y = acc[i][1] + bias.y;
        o.z = acc[i][2] + bias.z;
        o.w = acc[i][3] + bias.w;
        *reinterpret_cast<float4*>(&g_Hi[(size_t)(bm + ty*4 + i) * Cq + bn + tx*4]) = o;
    }
}

// ---------------------------------------------------------------------------
// K2: per-head MLP logits.
//   f_j = relu( sum_h Hi[t][i*96+h] * W1[i][j][h] + b1[i][j] )   j in [0,384)
//   Al[t][i*96+h] = sum_j f_j * W2[i][h][j] + b2[i][h]
// Thread-per-token: hi[96] and acc[96] live in registers; W1 / W2^T chunks
// staged in smem and read as broadcast LDS.128 (1 wavefront each).
// ---------------------------------------------------------------------------
__global__ __launch_bounds__(256, 1) void k2_mlp(
    const float* __restrict__ W1, const float* __restrict__ b1,
    const float* __restrict__ W2, const float* __restrict__ b2)
{
    __shared__ float W1s[64 * 96];   // 24 KB: rows j_local, cols h
    __shared__ float W2s[64 * 96];   // 24 KB: transposed, rows j_local, cols h
    __shared__ float b1s[64];

    const int head  = blockIdx.y;
    const int token = blockIdx.x * 256 + threadIdx.x;
    const size_t base = (size_t)token * Cq + head * HDq;

    float4 hv[24], av[24];
    #pragma unroll
    for (int q = 0; q < 24; q++)
        hv[q] = *reinterpret_cast<const float4*>(&g_Hi[base + q*4]);
    #pragma unroll
    for (int q = 0; q < 24; q++)
        av[q] = *reinterpret_cast<const float4*>(&b2[head*HDq + q*4]);

    const float* W1h = W1 + (size_t)head * HIDq * HDq;  // [j][h]
    const float* W2h = W2 + (size_t)head * HDq * HIDq;  // [h][j]
    const float* b1h = b1 + head * HIDq;

    for (int jc = 0; jc < HIDq; jc += 64) {
        __syncthreads();
        // W1 chunk: contiguous 64x96 block
        for (int idx = threadIdx.x; idx < 64*96; idx += 256)
            W1s[idx] = W1h[(size_t)jc * 96 + idx];
        // W2 chunk transposed: W2s[jl*96 + h] = W2h[h*384 + jc + jl]
        for (int idx = threadIdx.x; idx < 64*96; idx += 256) {
            int jl = idx & 63, h = idx >> 6;
            W2s[jl*96 + h] = W2h[(size_t)h * HIDq + jc + jl];
        }
        if (threadIdx.x < 64) b1s[threadIdx.x] = b1h[jc + threadIdx.x];
        __syncthreads();

        for (int j = 0; j < 64; j++) {
            // dot(hi, W1 row) with 4-way split accumulators (break FMA chain)
            float s0 = 0.f, s1 = 0.f, s2 = 0.f, s3 = 0.f;
            const float4* w1r = reinterpret_cast<const float4*>(&W1s[j*96]);
            #pragma unroll
            for (int q = 0; q < 24; q++) {
                float4 w = w1r[q];
                s0 = fmaf(w.x, hv[q].x, s0);
                s1 = fmaf(w.y, hv[q].y, s1);
                s2 = fmaf(w.z, hv[q].z, s2);
                s3 = fmaf(w.w, hv[q].w, s3);
            }
            float f = fmaxf((s0 + s1) + (s2 + s3) + b1s[j], 0.f);

            const float4* w2r = reinterpret_cast<const float4*>(&W2s[j*96]);
            #pragma unroll
            for (int q = 0; q < 24; q++) {
                float4 w = w2r[q];
                av[q].x = fmaf(f, w.x, av[q].x);
                av[q].y = fmaf(f, w.y, av[q].y);
                av[q].z = fmaf(f, w.z, av[q].z);
                av[q].w = fmaf(f, w.w, av[q].w);
            }
        }
    }

    #pragma unroll
    for (int q = 0; q < 24; q++)
        *reinterpret_cast<float4*>(&g_Al[base + q*4]) = av[q];
}

// ---------------------------------------------------------------------------
// K3: masked online softmax over s + weighted pool.
// One CTA per batch row b; thread owns 3 channels (tid, tid+256, tid+512).
// Polynomial exp2 (FMA pipe) instead of MUFU __expf.
// ---------------------------------------------------------------------------
__device__ __forceinline__ float fexp(float x) {
    x = fmaxf(x, -80.f);                       // handles -inf (sentinel max)
    float t  = x * 1.4426950408889634f;        // x * log2(e)
    float fi = floorf(t);
    float f  = t - fi;                         // [0,1)
    float p  = 1.8775767e-3f;
    p = fmaf(p, f, 8.9893397e-3f);
    p = fmaf(p, f, 5.5826318e-2f);
    p = fmaf(p, f, 2.4015361e-1f);
    p = fmaf(p, f, 6.9315308e-1f);
    p = fmaf(p, f, 1.0f);                      // ~= 2^f
    return __int_as_float(__float_as_int(p) + (((int)fi) << 23));  // * 2^fi
}

__global__ __launch_bounds__(256) void k3_pool(
    const float* __restrict__ mask, float* __restrict__ out)
{
    const int b   = blockIdx.x;
    const int tid = threadIdx.x;
    const size_t rowbase = (size_t)b * Sq * Cq;

    float m0 = -INFINITY, m1 = -INFINITY, m2 = -INFINITY;
    float l0 = 0.f, l1 = 0.f, l2 = 0.f;
    float a0 = 0.f, a1 = 0.f, a2 = 0.f;

    for (int s = 0; s < Sq; s++) {
        if (mask[b*Sq + s] > 0.5f) {   // prefix mask: uniform across block
            size_t t = rowbase + (size_t)s * Cq;
            float x0 = g_Al[t + tid      ], h0 = g_Hi[t + tid      ];
            float x1 = g_Al[t + tid + 256], h1 = g_Hi[t + tid + 256];
            float x2 = g_Al[t + tid + 512], h2 = g_Hi[t + tid + 512];

            float n0 = fmaxf(m0, x0), sc0 = fexp(m0 - n0), w0 = fexp(x0 - n0);
            l0 = fmaf(l0, sc0, w0); a0 = fmaf(a0, sc0, w0 * h0); m0 = n0;
            float n1 = fmaxf(m1, x1), sc1 = fexp(m1 - n1), w1 = fexp(x1 - n1);
            l1 = fmaf(l1, sc1, w1); a1 = fmaf(a1, sc1, w1 * h1); m1 = n1;
            float n2 = fmaxf(m2, x2), sc2 = fexp(m2 - n2), w2 = fexp(x2 - n2);
            l2 = fmaf(l2, sc2, w2); a2 = fmaf(a2, sc2, w2 * h2); m2 = n2;
        }
    }

    out[(size_t)b * Cq + tid      ] = a0 / l0;
    out[(size_t)b * Cq + tid + 256] = a1 / l1;
    out[(size_t)b * Cq + tid + 512] = a2 / l2;
}

// ---------------------------------------------------------------------------
extern "C" void kernel_launch(void* const* d_in, const int* in_sizes, int n_in,
                              void* d_out, int out_size)
{
    const float* X    = (const float*)d_in[0];   // (B,S,D)
    const float* mask = (const float*)d_in[1];   // (B,S)
    const float* P    = (const float*)d_in[2];   // (NH,HD,D) -> flat [c][d]
    const float* bP   = (const float*)d_in[3];   // (NH,HD)   -> flat [c]
    const float* W1   = (const float*)d_in[4];   // (NH,HID,HD)
    const float* b1   = (const float*)d_in[5];   // (NH,HID)
    const float* W2   = (const float*)d_in[6];   // (NH,HD,HID)
    const float* b2   = (const float*)d_in[7];   // (NH,HD)
    float* out = (float*)d_out;                  // (B, NH*HD)

    dim3 g1(Mq / 64, Cq / 64);
    k1_proj<<<g1, 256>>>(X, P, bP);

    dim3 g2(Mq / 256, NHq);
    k2_mlp<<<g2, 256>>>(W1, b1, W2, b2);

    k3_pool<<<Bq, 256>>>(mask, out);
}

// round 3
// speedup vs baseline: 3.6757x; 3.6757x over previous
#include <cuda_runtime.h>
#include <cuda_bf16.h>
#include <math.h>
#include <stdint.h>

#define Bq   128
#define Sq   512
#define Dq   768
#define NHq  8
#define HDq  96
#define HIDq 384
#define Cq   768            // NH*HD
#define Mq   (Bq*Sq)        // 65536 tokens

// ---------------------------------------------------------------------------
// Scratch (__device__ globals; cudaMalloc is forbidden)
// ---------------------------------------------------------------------------
__device__ float          g_Hi [(size_t)Mq * Cq];   // 192 MB projections fp32
__device__ float          g_Al [(size_t)Mq * Cq];   // 192 MB logits fp32
__device__ __nv_bfloat16  g_Hib[(size_t)Mq * Cq];   // 96 MB  projections bf16
__device__ __nv_bfloat16  g_Xh [(size_t)Mq * Dq];   // 96 MB  X hi
__device__ __nv_bfloat16  g_Xl [(size_t)Mq * Dq];   // 96 MB  X lo
__device__ __nv_bfloat16  g_Ph [(size_t)Cq * Dq];   // 1.2 MB P hi
__device__ __nv_bfloat16  g_Pl [(size_t)Cq * Dq];   // 1.2 MB P lo
__device__ __nv_bfloat16  g_W1b[(size_t)NHq * HIDq * HDq];
__device__ __nv_bfloat16  g_W2b[(size_t)NHq * HDq * HIDq];

// ---------------------------------------------------------------------------
// Generic-PTX tensor-core helpers (valid on plain sm_103 target)
// ---------------------------------------------------------------------------
__device__ __forceinline__ uint32_t smem_u32(const void* p) {
    uint32_t a;
    asm("{ .reg .u64 t; cvta.to.shared.u64 t, %1; cvt.u32.u64 %0, t; }"
        : "=r"(a) : "l"(p));
    return a;
}
__device__ __forceinline__ void mma16816(float* c, const uint32_t* a, const uint32_t* b) {
    asm volatile("mma.sync.aligned.m16n8k16.row.col.f32.bf16.bf16.f32 "
        "{%0,%1,%2,%3}, {%4,%5,%6,%7}, {%8,%9}, {%0,%1,%2,%3};"
        : "+f"(c[0]), "+f"(c[1]), "+f"(c[2]), "+f"(c[3])
        : "r"(a[0]), "r"(a[1]), "r"(a[2]), "r"(a[3]), "r"(b[0]), "r"(b[1]));
}
__device__ __forceinline__ void ldsm_x4(uint32_t* r, uint32_t addr) {
    asm volatile("ldmatrix.sync.aligned.m8n8.x4.shared.b16 {%0,%1,%2,%3}, [%4];"
        : "=r"(r[0]), "=r"(r[1]), "=r"(r[2]), "=r"(r[3]) : "r"(addr));
}
__device__ __forceinline__ void cp16(uint32_t dst, const void* src) {
    asm volatile("cp.async.cg.shared.global [%0], [%1], 16;" :: "r"(dst), "l"(src));
}
#define CP_COMMIT()  asm volatile("cp.async.commit_group;" ::: "memory")
#define CP_WAIT(n)   asm volatile("cp.async.wait_group %0;" :: "n"(n) : "memory")
#define SW(o)        ((o) ^ (((o) >> 3) & 0x70))   // SW128 swizzle (128B rows)

// ---------------------------------------------------------------------------
// K0a: fp32 -> bf16 hi/lo split.  K0b: fp32 -> bf16 convert.
// ---------------------------------------------------------------------------
__global__ __launch_bounds__(256) void k0_split(
    const float* __restrict__ src, __nv_bfloat16* __restrict__ hi,
    __nv_bfloat16* __restrict__ lo, int n4)
{
    int i = blockIdx.x * 256 + threadIdx.x;
    if (i >= n4) return;
    float4 v = reinterpret_cast<const float4*>(src)[i];
    __nv_bfloat16 h0 = __float2bfloat16(v.x), h1 = __float2bfloat16(v.y);
    __nv_bfloat16 h2 = __float2bfloat16(v.z), h3 = __float2bfloat16(v.w);
    ushort4 H, L;
    H.x = __bfloat16_as_ushort(h0); H.y = __bfloat16_as_ushort(h1);
    H.z = __bfloat16_as_ushort(h2); H.w = __bfloat16_as_ushort(h3);
    L.x = __bfloat16_as_ushort(__float2bfloat16(v.x - __bfloat162float(h0)));
    L.y = __bfloat16_as_ushort(__float2bfloat16(v.y - __bfloat162float(h1)));
    L.z = __bfloat16_as_ushort(__float2bfloat16(v.z - __bfloat162float(h2)));
    L.w = __bfloat16_as_ushort(__float2bfloat16(v.w - __bfloat162float(h3)));
    reinterpret_cast<ushort4*>(hi)[i] = H;
    reinterpret_cast<ushort4*>(lo)[i] = L;
}

__global__ __launch_bounds__(256) void k0_cvt(
    const float* __restrict__ src, __nv_bfloat16* __restrict__ dst, int n4)
{
    int i = blockIdx.x * 256 + threadIdx.x;
    if (i >= n4) return;
    float4 v = reinterpret_cast<const float4*>(src)[i];
    ushort4 H;
    H.x = __bfloat16_as_ushort(__float2bfloat16(v.x));
    H.y = __bfloat16_as_ushort(__float2bfloat16(v.y));
    H.z = __bfloat16_as_ushort(__float2bfloat16(v.z));
    H.w = __bfloat16_as_ushort(__float2bfloat16(v.w));
    reinterpret_cast<ushort4*>(dst)[i] = H;
}

// ---------------------------------------------------------------------------
// K1: HMMA bf16 3-split GEMM.  Hi = X @ P^T + bP  (65536 x 768 x 768)
// 128x128 tile/CTA, K-chunks of 64, virtual K = 3*768 (Ah.Bh + Ah.Bl + Al.Bh),
// double-buffered cp.async, 8 warps in 4(m) x 2(n), warp tile 32x64.
// ---------------------------------------------------------------------------
#define K1_CH   16384                       // bytes per 128x64 bf16 tile
#define K1_SMEM (4 * K1_CH)                 // 2 stages x (A+B)

__global__ __launch_bounds__(256) void k1_mma(
    const __nv_bfloat16* __restrict__ Xh, const __nv_bfloat16* __restrict__ Xl,
    const __nv_bfloat16* __restrict__ Ph, const __nv_bfloat16* __restrict__ Pl,
    const float* __restrict__ bP)
{
    extern __shared__ char smem[];
    const uint32_t sb = smem_u32(smem);
    const int tid  = threadIdx.x;
    const int wid  = tid >> 5, lane = tid & 31;
    const int bm   = blockIdx.x * 128, bn = blockIdx.y * 128;
    const int wm   = (wid >> 1) * 32,  wn = (wid & 1) * 64;

    float acc[2][8][4];
    #pragma unroll
    for (int a = 0; a < 2; a++)
        #pragma unroll
        for (int b = 0; b < 8; b++)
            #pragma unroll
            for (int c = 0; c < 4; c++) acc[a][b][c] = 0.f;

    auto load = [&](int kv, int s) {
        const int term = kv / 12, koff = (kv % 12) * 64;
        const __nv_bfloat16* A  = (term < 2) ? Xh : Xl;
        const __nv_bfloat16* Bp = (term == 1) ? Pl : Ph;
        const uint32_t sa = sb + s * 2 * K1_CH;
        const uint32_t sB = sa + K1_CH;
        #pragma unroll
        for (int t = 0; t < 4; t++) {
            int idx = tid + t * 256;               // 0..1023
            int row = idx >> 3, c16 = idx & 7;
            uint32_t off = SW(row * 128 + c16 * 16);
            cp16(sa + off, A  + (size_t)(bm + row) * Dq + koff + c16 * 8);
            cp16(sB + off, Bp + (size_t)(bn + row) * Dq + koff + c16 * 8);
        }
        CP_COMMIT();
    };

    load(0, 0);
    const int NKV = 36;                            // 3 terms x 12 chunks
    for (int kv = 0; kv < NKV; kv++) {
        const int s = kv & 1;
        if (kv + 1 < NKV) { load(kv + 1, s ^ 1); CP_WAIT(1); }
        else              { CP_WAIT(0); }
        __syncthreads();

        const uint32_t sa = sb + s * 2 * K1_CH;
        const uint32_t sB = sa + K1_CH;
        #pragma unroll
        for (int ks = 0; ks < 4; ks++) {
            uint32_t afr[2][4], bfr[4][4];
            #pragma unroll
            for (int mf = 0; mf < 2; mf++) {
                int row = wm + mf * 16 + (lane & 15);
                ldsm_x4(afr[mf], sa + SW(row * 128 + ((lane >> 4) + ks * 2) * 16));
            }
            #pragma unroll
            for (int p = 0; p < 4; p++) {
                int g = lane >> 3;
                int row = wn + p * 16 + ((g >> 1) * 8) + (lane & 7);
                ldsm_x4(bfr[p], sB + SW(row * 128 + (ks * 2 + (g & 1)) * 16));
            }
            #pragma unroll
            for (int mf = 0; mf < 2; mf++)
                #pragma unroll
                for (int nf = 0; nf < 8; nf++)
                    mma16816(acc[mf][nf], afr[mf], &bfr[nf >> 1][(nf & 1) * 2]);
        }
        __syncthreads();
    }

    // epilogue: D + bias -> g_Hi (fp32) and g_Hib (bf16)
    #pragma unroll
    for (int mf = 0; mf < 2; mf++) {
        const int m0 = bm + wm + mf * 16 + (lane >> 2);
        #pragma unroll
        for (int nf = 0; nf < 8; nf++) {
            const int n = bn + wn + nf * 8 + 2 * (lane & 3);
            const float b0 = __ldg(&bP[n]), b1 = __ldg(&bP[n + 1]);
            float v0 = acc[mf][nf][0] + b0, v1 = acc[mf][nf][1] + b1;
            float v2 = acc[mf][nf][2] + b0, v3 = acc[mf][nf][3] + b1;
            *reinterpret_cast<float2*>(&g_Hi[(size_t)m0 * Cq + n])       = make_float2(v0, v1);
            *reinterpret_cast<float2*>(&g_Hi[(size_t)(m0 + 8) * Cq + n]) = make_float2(v2, v3);
            __nv_bfloat162 p0 = __floats2bfloat162_rn(v0, v1);
            __nv_bfloat162 p1 = __floats2bfloat162_rn(v2, v3);
            *reinterpret_cast<__nv_bfloat162*>(&g_Hib[(size_t)m0 * Cq + n])       = p0;
            *reinterpret_cast<__nv_bfloat162*>(&g_Hib[(size_t)(m0 + 8) * Cq + n]) = p1;
        }
    }
}

// ---------------------------------------------------------------------------
// K2: fused 2-layer MLP on HMMA.  A = W2(relu(W1(Hi)+b1))+b2 per head.
// CTA: 128 tokens x 1 head. Hidden (384) processed in 3 chunks of 128;
// relu intermediate staged in smem bf16; layer2 accumulates across chunks.
// smem (bytes): Hi[128][104]b @0, W1c[128][104]b @26624,
//               F[128][136]b @53248, W2c[96][136]b @88064  -> total 114176.
// ---------------------------------------------------------------------------
#define OHI  0
#define OW1  26624
#define OF   53248
#define OW2  88064
#define K2_SMEM 114176
#define SHI  208     // bytes/row (96 bf16 + pad 8)
#define SF   272     // bytes/row (128 bf16 + pad 8)

__global__ __launch_bounds__(256, 1) void k2_mlp(
    const float* __restrict__ b1, const float* __restrict__ b2)
{
    extern __shared__ char smem[];
    const uint32_t sb = smem_u32(smem);
    const int tid = threadIdx.x, wid = tid >> 5, lane = tid & 31;
    const int head  = blockIdx.y;
    const int mtile = blockIdx.x * 128;
    const int wm  = (wid >> 1) * 32;
    const int wn1 = (wid & 1) * 64;    // layer1 N=128 split
    const int wn2 = (wid & 1) * 48;    // layer2 N=96 split

    const __nv_bfloat16* W1h = g_W1b + (size_t)head * HIDq * HDq;
    const __nv_bfloat16* W2h = g_W2b + (size_t)head * HDq * HIDq;
    const float* b1h = b1 + head * HIDq;
    const float* b2h = b2 + head * HDq;

    // stage Hi tile (128 x 96 bf16, stride 208B)
    #pragma unroll
    for (int t = 0; t < 6; t++) {
        int idx = tid + t * 256;          // 0..1535
        int row = idx / 12, c16 = idx % 12;
        cp16(sb + OHI + row * SHI + c16 * 16,
             g_Hib + (size_t)(mtile + row) * Cq + head * HDq + c16 * 8);
    }
    CP_COMMIT();

    float acc2[2][6][4];
    #pragma unroll
    for (int a = 0; a < 2; a++)
        #pragma unroll
        for (int b = 0; b < 6; b++)
            #pragma unroll
            for (int c = 0; c < 4; c++) acc2[a][b][c] = 0.f;

    for (int jc = 0; jc < 3; jc++) {
        const int j0 = jc * 128;
        __syncthreads();                  // prior chunk's reads of W tiles done
        #pragma unroll
        for (int t = 0; t < 6; t++) {     // W1 chunk: 128 rows x 96 bf16
            int idx = tid + t * 256;
            int row = idx / 12, c16 = idx % 12;
            cp16(sb + OW1 + row * SHI + c16 * 16,
                 W1h + (size_t)(j0 + row) * HDq + c16 * 8);
        }
        #pragma unroll
        for (int t = 0; t < 6; t++) {     // W2 chunk: 96 rows x 128 bf16
            int idx = tid + t * 256;
            int row = idx >> 4, c16 = idx & 15;
            cp16(sb + OW2 + row * SF + c16 * 16,
                 W2h + (size_t)row * HIDq + j0 + c16 * 8);
        }
        CP_COMMIT();
        CP_WAIT(0);
        __syncthreads();

        // ---- layer 1: F = relu(Hi @ W1c^T + b1) ----
        float acc1[2][8][4];
        #pragma unroll
        for (int a = 0; a < 2; a++)
            #pragma unroll
            for (int b = 0; b < 8; b++)
                #pragma unroll
                for (int c = 0; c < 4; c++) acc1[a][b][c] = 0.f;

        #pragma unroll
        for (int ks = 0; ks < 6; ks++) {  // K = 96
            uint32_t afr[2][4], bfr[4][4];
            #pragma unroll
            for (int mf = 0; mf < 2; mf++) {
                int row = wm + mf * 16 + (lane & 15);
                ldsm_x4(afr[mf], sb + OHI + row * SHI + (lane >> 4) * 16 + ks * 32);
            }
            #pragma unroll
            for (int p = 0; p < 4; p++) {
                int g = lane >> 3;
                int row = wn1 + p * 16 + (g >> 1) * 8 + (lane & 7);
                ldsm_x4(bfr[p], sb + OW1 + row * SHI + (g & 1) * 16 + ks * 32);
            }
            #pragma unroll
            for (int mf = 0; mf < 2; mf++)
                #pragma unroll
                for (int nf = 0; nf < 8; nf++)
                    mma16816(acc1[mf][nf], afr[mf], &bfr[nf >> 1][(nf & 1) * 2]);
        }

        // relu + b1, pack bf16x2 into F tile
        #pragma unroll
        for (int mf = 0; mf < 2; mf++) {
            const int m0 = wm + mf * 16 + (lane >> 2);
            #pragma unroll
            for (int nf = 0; nf < 8; nf++) {
                const int jl = wn1 + nf * 8 + 2 * (lane & 3);
                const float c0 = __ldg(&b1h[j0 + jl]), c1 = __ldg(&b1h[j0 + jl + 1]);
                float v0 = fmaxf(acc1[mf][nf][0] + c0, 0.f);
                float v1 = fmaxf(acc1[mf][nf][1] + c1, 0.f);
                float v2 = fmaxf(acc1[mf][nf][2] + c0, 0.f);
                float v3 = fmaxf(acc1[mf][nf][3] + c1, 0.f);
                __nv_bfloat162 p0 = __floats2bfloat162_rn(v0, v1);
                __nv_bfloat162 p1 = __floats2bfloat162_rn(v2, v3);
                *reinterpret_cast<uint32_t*>(smem + OF + m0 * SF + jl * 2) =
                    *reinterpret_cast<uint32_t*>(&p0);
                *reinterpret_cast<uint32_t*>(smem + OF + (m0 + 8) * SF + jl * 2) =
                    *reinterpret_cast<uint32_t*>(&p1);
            }
        }
        __syncthreads();

        // ---- layer 2 partial: acc2 += F @ W2c^T ----
        #pragma unroll
        for (int ks = 0; ks < 8; ks++) {  // K = 128
            uint32_t afr[2][4], bfr[3][4];
            #pragma unroll
            for (int mf = 0; mf < 2; mf++) {
                int row = wm + mf * 16 + (lane & 15);
                ldsm_x4(afr[mf], sb + OF + row * SF + (lane >> 4) * 16 + ks * 32);
            }
            #pragma unroll
            for (int p = 0; p < 3; p++) {
                int g = lane >> 3;
                int row = wn2 + p * 16 + (g >> 1) * 8 + (lane & 7);
                ldsm_x4(bfr[p], sb + OW2 + row * SF + (g & 1) * 16 + ks * 32);
            }
            #pragma unroll
            for (int mf = 0; mf < 2; mf++)
                #pragma unroll
                for (int nf = 0; nf < 6; nf++)
                    mma16816(acc2[mf][nf], afr[mf], &bfr[nf >> 1][(nf & 1) * 2]);
        }
    }

    // epilogue: logits + b2 -> g_Al fp32
    #pragma unroll
    for (int mf = 0; mf < 2; mf++) {
        const int m0 = mtile + wm + mf * 16 + (lane >> 2);
        #pragma unroll
        for (int nf = 0; nf < 6; nf++) {
            const int n = wn2 + nf * 8 + 2 * (lane & 3);
            const float c0 = __ldg(&b2h[n]), c1 = __ldg(&b2h[n + 1]);
            *reinterpret_cast<float2*>(&g_Al[(size_t)m0 * Cq + head * HDq + n]) =
                make_float2(acc2[mf][nf][0] + c0, acc2[mf][nf][1] + c1);
            *reinterpret_cast<float2*>(&g_Al[(size_t)(m0 + 8) * Cq + head * HDq + n]) =
                make_float2(acc2[mf][nf][2] + c0, acc2[mf][nf][3] + c1);
        }
    }
}

// ---------------------------------------------------------------------------
// K3: masked online softmax-pool (unchanged from passing R1 kernel)
// ---------------------------------------------------------------------------
__device__ __forceinline__ float fexp(float x) {
    x = fmaxf(x, -80.f);
    float t  = x * 1.4426950408889634f;
    float fi = floorf(t);
    float f  = t - fi;
    float p  = 1.8775767e-3f;
    p = fmaf(p, f, 8.9893397e-3f);
    p = fmaf(p, f, 5.5826318e-2f);
    p = fmaf(p, f, 2.4015361e-1f);
    p = fmaf(p, f, 6.9315308e-1f);
    p = fmaf(p, f, 1.0f);
    return __int_as_float(__float_as_int(p) + (((int)fi) << 23));
}

__global__ __launch_bounds__(256) void k3_pool(
    const float* __restrict__ mask, float* __restrict__ out)
{
    const int b   = blockIdx.x;
    const int tid = threadIdx.x;
    const size_t rowbase = (size_t)b * Sq * Cq;

    float m0 = -INFINITY, m1 = -INFINITY, m2 = -INFINITY;
    float l0 = 0.f, l1 = 0.f, l2 = 0.f;
    float a0 = 0.f, a1 = 0.f, a2 = 0.f;

    for (int s = 0; s < Sq; s++) {
        if (mask[b*Sq + s] > 0.5f) {
            size_t t = rowbase + (size_t)s * Cq;
            float x0 = g_Al[t + tid      ], h0 = g_Hi[t + tid      ];
            float x1 = g_Al[t + tid + 256], h1 = g_Hi[t + tid + 256];
            float x2 = g_Al[t + tid + 512], h2 = g_Hi[t + tid + 512];

            float n0 = fmaxf(m0, x0), sc0 = fexp(m0 - n0), w0 = fexp(x0 - n0);
            l0 = fmaf(l0, sc0, w0); a0 = fmaf(a0, sc0, w0 * h0); m0 = n0;
            float n1 = fmaxf(m1, x1), sc1 = fexp(m1 - n1), w1 = fexp(x1 - n1);
            l1 = fmaf(l1, sc1, w1); a1 = fmaf(a1, sc1, w1 * h1); m1 = n1;
            float n2 = fmaxf(m2, x2), sc2 = fexp(m2 - n2), w2 = fexp(x2 - n2);
            l2 = fmaf(l2, sc2, w2); a2 = fmaf(a2, sc2, w2 * h2); m2 = n2;
        }
    }

    out[(size_t)b * Cq + tid      ] = a0 / l0;
    out[(size_t)b * Cq + tid + 256] = a1 / l1;
    out[(size_t)b * Cq + tid + 512] = a2 / l2;
}

// ---------------------------------------------------------------------------
extern "C" void kernel_launch(void* const* d_in, const int* in_sizes, int n_in,
                              void* d_out, int out_size)
{
    const float* X    = (const float*)d_in[0];   // (B,S,D)
    const float* mask = (const float*)d_in[1];   // (B,S)
    const float* P    = (const float*)d_in[2];   // (NH,HD,D)
    const float* bP   = (const float*)d_in[3];   // (NH,HD)
    const float* W1   = (const float*)d_in[4];   // (NH,HID,HD)
    const float* b1   = (const float*)d_in[5];   // (NH,HID)
    const float* W2   = (const float*)d_in[6];   // (NH,HD,HID)
    const float* b2   = (const float*)d_in[7];   // (NH,HD)
    float* out = (float*)d_out;                  // (B, NH*HD)

    cudaFuncSetAttribute(k1_mma, cudaFuncAttributeMaxDynamicSharedMemorySize, K1_SMEM);
    cudaFuncSetAttribute(k2_mlp, cudaFuncAttributeMaxDynamicSharedMemorySize, K2_SMEM);

    __nv_bfloat16 *Xh, *Xl, *Ph, *Pl, *W1b, *W2b;
    cudaGetSymbolAddress((void**)&Xh,  g_Xh);
    cudaGetSymbolAddress((void**)&Xl,  g_Xl);
    cudaGetSymbolAddress((void**)&Ph,  g_Ph);
    cudaGetSymbolAddress((void**)&Pl,  g_Pl);
    cudaGetSymbolAddress((void**)&W1b, g_W1b);
    cudaGetSymbolAddress((void**)&W2b, g_W2b);

    // K0: bf16 splits / converts
    {
        int n4x = Mq * Dq / 4;
        k0_split<<<(n4x + 255) / 256, 256>>>(X, Xh, Xl, n4x);
        int n4p = Cq * Dq / 4;
        k0_split<<<(n4p + 255) / 256, 256>>>(P, Ph, Pl, n4p);
        int n4w = NHq * HIDq * HDq / 4;
        k0_cvt<<<(n4w + 255) / 256, 256>>>(W1, W1b, n4w);
        k0_cvt<<<(n4w + 255) / 256, 256>>>(W2, W2b, n4w);
    }

    // K1: projection GEMM (HMMA, 3-split bf16)
    dim3 g1(Mq / 128, Cq / 128);
    k1_mma<<<g1, 256, K1_SMEM>>>(Xh, Xl, Ph, Pl, bP);

    // K2: fused MLP logits (HMMA bf16)
    dim3 g2(Mq / 128, NHq);
    k2_mlp<<<g2, 256, K2_SMEM>>>(b1, b2);

    // K3: masked softmax pooling
    k3_pool<<<Bq, 256>>>(mask, out);
}

// round 4
// speedup vs baseline: 4.2074x; 1.1446x over previous
#include <cuda_runtime.h>
#include <cuda_bf16.h>
#include <math.h>
#include <stdint.h>

#define Bq   128
#define Sq   512
#define Dq   768
#define NHq  8
#define HDq  96
#define HIDq 384
#define Cq   768            // NH*HD
#define Mq   (Bq*Sq)        // 65536 tokens

// ---------------------------------------------------------------------------
// Scratch (__device__ globals; cudaMalloc is forbidden)
// ---------------------------------------------------------------------------
__device__ float          g_Hi [(size_t)Mq * Cq];   // 192 MB projections fp32
__device__ float          g_Al [(size_t)Mq * Cq];   // 192 MB logits fp32
__device__ __nv_bfloat16  g_Hib[(size_t)Mq * Cq];   // 96 MB  projections bf16
__device__ __nv_bfloat16  g_Xh [(size_t)Mq * Dq];   // 96 MB  X hi
__device__ __nv_bfloat16  g_Xl [(size_t)Mq * Dq];   // 96 MB  X lo
__device__ __nv_bfloat16  g_Ph [(size_t)Cq * Dq];   // 1.2 MB P hi
__device__ __nv_bfloat16  g_Pl [(size_t)Cq * Dq];   // 1.2 MB P lo
__device__ __nv_bfloat16  g_W1b[(size_t)NHq * HIDq * HDq];
__device__ __nv_bfloat16  g_W2b[(size_t)NHq * HDq * HIDq];

// ---------------------------------------------------------------------------
// Generic-PTX tensor-core helpers (valid on plain sm_103 target)
// ---------------------------------------------------------------------------
__device__ __forceinline__ uint32_t smem_u32(const void* p) {
    uint32_t a;
    asm("{ .reg .u64 t; cvta.to.shared.u64 t, %1; cvt.u32.u64 %0, t; }"
        : "=r"(a) : "l"(p));
    return a;
}
__device__ __forceinline__ void mma16816(float* c, const uint32_t* a, const uint32_t* b) {
    asm volatile("mma.sync.aligned.m16n8k16.row.col.f32.bf16.bf16.f32 "
        "{%0,%1,%2,%3}, {%4,%5,%6,%7}, {%8,%9}, {%0,%1,%2,%3};"
        : "+f"(c[0]), "+f"(c[1]), "+f"(c[2]), "+f"(c[3])
        : "r"(a[0]), "r"(a[1]), "r"(a[2]), "r"(a[3]), "r"(b[0]), "r"(b[1]));
}
__device__ __forceinline__ void ldsm_x4(uint32_t* r, uint32_t addr) {
    asm volatile("ldmatrix.sync.aligned.m8n8.x4.shared.b16 {%0,%1,%2,%3}, [%4];"
        : "=r"(r[0]), "=r"(r[1]), "=r"(r[2]), "=r"(r[3]) : "r"(addr));
}
__device__ __forceinline__ void cp16(uint32_t dst, const void* src) {
    asm volatile("cp.async.cg.shared.global [%0], [%1], 16;" :: "r"(dst), "l"(src));
}
#define CP_COMMIT()  asm volatile("cp.async.commit_group;" ::: "memory")
#define CP_WAIT(n)   asm volatile("cp.async.wait_group %0;" :: "n"(n) : "memory")
#define SW(o)        ((o) ^ (((o) >> 3) & 0x70))   // SW128 swizzle (128B rows)

// ---------------------------------------------------------------------------
// K0a: fp32 -> bf16 hi/lo split.  K0b: fp32 -> bf16 convert.
// ---------------------------------------------------------------------------
__global__ __launch_bounds__(256) void k0_split(
    const float* __restrict__ src, __nv_bfloat16* __restrict__ hi,
    __nv_bfloat16* __restrict__ lo, int n4)
{
    int i = blockIdx.x * 256 + threadIdx.x;
    if (i >= n4) return;
    float4 v = reinterpret_cast<const float4*>(src)[i];
    __nv_bfloat16 h0 = __float2bfloat16(v.x), h1 = __float2bfloat16(v.y);
    __nv_bfloat16 h2 = __float2bfloat16(v.z), h3 = __float2bfloat16(v.w);
    ushort4 H, L;
    H.x = __bfloat16_as_ushort(h0); H.y = __bfloat16_as_ushort(h1);
    H.z = __bfloat16_as_ushort(h2); H.w = __bfloat16_as_ushort(h3);
    L.x = __bfloat16_as_ushort(__float2bfloat16(v.x - __bfloat162float(h0)));
    L.y = __bfloat16_as_ushort(__float2bfloat16(v.y - __bfloat162float(h1)));
    L.z = __bfloat16_as_ushort(__float2bfloat16(v.z - __bfloat162float(h2)));
    L.w = __bfloat16_as_ushort(__float2bfloat16(v.w - __bfloat162float(h3)));
    reinterpret_cast<ushort4*>(hi)[i] = H;
    reinterpret_cast<ushort4*>(lo)[i] = L;
}

__global__ __launch_bounds__(256) void k0_cvt(
    const float* __restrict__ src, __nv_bfloat16* __restrict__ dst, int n4)
{
    int i = blockIdx.x * 256 + threadIdx.x;
    if (i >= n4) return;
    float4 v = reinterpret_cast<const float4*>(src)[i];
    ushort4 H;
    H.x = __bfloat16_as_ushort(__float2bfloat16(v.x));
    H.y = __bfloat16_as_ushort(__float2bfloat16(v.y));
    H.z = __bfloat16_as_ushort(__float2bfloat16(v.z));
    H.w = __bfloat16_as_ushort(__float2bfloat16(v.w));
    reinterpret_cast<ushort4*>(dst)[i] = H;
}

// ---------------------------------------------------------------------------
// K1: HMMA bf16 3-split GEMM.  Hi = X @ P^T + bP  (65536 x 768 x 768)
// 128x128 tile/CTA; 12 physical K-chunks of 64; per chunk loads ALL 4 tiles
// (Xh,Xl,Ph,Pl = 64KB) once and computes all 3 terms (Ah.Bh + Ah.Bl + Al.Bh).
// 3-stage cp.async pipeline (192KB smem), one __syncthreads per chunk.
// Grid: x = N-tile (6, fast) so consecutive CTAs share the streamed X tile.
// ---------------------------------------------------------------------------
#define K1_STG  65536
#define K1_SMEM (3 * K1_STG)     // 196608 bytes

__global__ __launch_bounds__(256) void k1_mma(
    const __nv_bfloat16* __restrict__ Xh, const __nv_bfloat16* __restrict__ Xl,
    const __nv_bfloat16* __restrict__ Ph, const __nv_bfloat16* __restrict__ Pl,
    const float* __restrict__ bP)
{
    extern __shared__ char smem[];
    const uint32_t sb = smem_u32(smem);
    const int tid  = threadIdx.x;
    const int wid  = tid >> 5, lane = tid & 31;
    const int bn   = blockIdx.x * 128, bm = blockIdx.y * 128;   // x = N (fast)
    const int wm   = (wid >> 1) * 32,  wn = (wid & 1) * 64;

    float acc[2][8][4];
    #pragma unroll
    for (int a = 0; a < 2; a++)
        #pragma unroll
        for (int b = 0; b < 8; b++)
            #pragma unroll
            for (int c = 0; c < 4; c++) acc[a][b][c] = 0.f;

    auto load_chunk = [&](int c, int s) {
        const int kb = c * 64;
        const uint32_t st = sb + s * K1_STG;
        #pragma unroll
        for (int t = 0; t < 4; t++) {
            int idx = tid + t * 256;               // 0..1023
            int row = idx >> 3, c16 = idx & 7;
            uint32_t off = SW(row * 128 + c16 * 16);
            const size_t gx = (size_t)(bm + row) * Dq + kb + c16 * 8;
            const size_t gp = (size_t)(bn + row) * Dq + kb + c16 * 8;
            cp16(st +         off, Xh + gx);
            cp16(st + 16384 + off, Xl + gx);
            cp16(st + 32768 + off, Ph + gp);
            cp16(st + 49152 + off, Pl + gp);
        }
        CP_COMMIT();
    };

    load_chunk(0, 0);
    load_chunk(1, 1);

    #pragma unroll 1
    for (int c = 0; c < 12; c++) {
        if (c < 10) { CP_WAIT(1); } else { CP_WAIT(0); }
        __syncthreads();
        if (c + 2 < 12) load_chunk(c + 2, (c + 2) % 3);

        const uint32_t st  = sb + (c % 3) * K1_STG;
        const uint32_t sAh = st, sAl = st + 16384, sBh = st + 32768, sBl = st + 49152;
        #pragma unroll
        for (int ks = 0; ks < 4; ks++) {
            uint32_t ah[2][4], al[2][4], bh[4][4], bl[4][4];
            #pragma unroll
            for (int mf = 0; mf < 2; mf++) {
                int row = wm + mf * 16 + (lane & 15);
                uint32_t off = SW(row * 128 + ((lane >> 4) + ks * 2) * 16);
                ldsm_x4(ah[mf], sAh + off);
                ldsm_x4(al[mf], sAl + off);
            }
            #pragma unroll
            for (int p = 0; p < 4; p++) {
                int g = lane >> 3;
                int row = wn + p * 16 + (g >> 1) * 8 + (lane & 7);
                uint32_t off = SW(row * 128 + (ks * 2 + (g & 1)) * 16);
                ldsm_x4(bh[p], sBh + off);
                ldsm_x4(bl[p], sBl + off);
            }
            #pragma unroll
            for (int mf = 0; mf < 2; mf++)
                #pragma unroll
                for (int nf = 0; nf < 8; nf++) {
                    mma16816(acc[mf][nf], ah[mf], &bh[nf >> 1][(nf & 1) * 2]);
                    mma16816(acc[mf][nf], ah[mf], &bl[nf >> 1][(nf & 1) * 2]);
                    mma16816(acc[mf][nf], al[mf], &bh[nf >> 1][(nf & 1) * 2]);
                }
        }
        // next iteration's top __syncthreads protects stage reuse
    }

    // epilogue: D + bias -> g_Hi (fp32) and g_Hib (bf16)
    #pragma unroll
    for (int mf = 0; mf < 2; mf++) {
        const int m0 = bm + wm + mf * 16 + (lane >> 2);
        #pragma unroll
        for (int nf = 0; nf < 8; nf++) {
            const int n = bn + wn + nf * 8 + 2 * (lane & 3);
            const float b0 = __ldg(&bP[n]), b1 = __ldg(&bP[n + 1]);
            float v0 = acc[mf][nf][0] + b0, v1 = acc[mf][nf][1] + b1;
            float v2 = acc[mf][nf][2] + b0, v3 = acc[mf][nf][3] + b1;
            *reinterpret_cast<float2*>(&g_Hi[(size_t)m0 * Cq + n])       = make_float2(v0, v1);
            *reinterpret_cast<float2*>(&g_Hi[(size_t)(m0 + 8) * Cq + n]) = make_float2(v2, v3);
            __nv_bfloat162 p0 = __floats2bfloat162_rn(v0, v1);
            __nv_bfloat162 p1 = __floats2bfloat162_rn(v2, v3);
            *reinterpret_cast<__nv_bfloat162*>(&g_Hib[(size_t)m0 * Cq + n])       = p0;
            *reinterpret_cast<__nv_bfloat162*>(&g_Hib[(size_t)(m0 + 8) * Cq + n]) = p1;
        }
    }
}

// ---------------------------------------------------------------------------
// K2: fused 2-layer MLP on HMMA.  A = W2(relu(W1(Hi)+b1))+b2 per head.
// CTA: 128 tokens x 1 head; hidden 384 in 3 chunks of 128; W double-buffered.
// Grid: x = head (8, fast) so the 8 heads of one token tile run adjacently
// and together read each Hib row once through L2.
// smem: Hi[128x208B]@0, F[128x272B]@26624, W1 x2 @61440, W2 x2 @114688.
// ---------------------------------------------------------------------------
#define OHI  0
#define OF   26624
#define OW1  61440
#define OW2  114688
#define W1SZ 26624      // 128 * 208
#define W2SZ 26112      // 96 * 272
#define K2_SMEM 166912
#define SHI  208        // bytes/row (96 bf16 + pad)
#define SF   272        // bytes/row (128 bf16 + pad)

__global__ __launch_bounds__(256, 1) void k2_mlp(
    const float* __restrict__ b1, const float* __restrict__ b2)
{
    extern __shared__ char smem[];
    const uint32_t sb = smem_u32(smem);
    const int tid = threadIdx.x, wid = tid >> 5, lane = tid & 31;
    const int head  = blockIdx.x;            // fast axis
    const int mtile = blockIdx.y * 128;
    const int wm  = (wid >> 1) * 32;
    const int wn1 = (wid & 1) * 64;
    const int wn2 = (wid & 1) * 48;

    const __nv_bfloat16* W1h = g_W1b + (size_t)head * HIDq * HDq;
    const __nv_bfloat16* W2h = g_W2b + (size_t)head * HDq * HIDq;
    const float* b1h = b1 + head * HIDq;
    const float* b2h = b2 + head * HDq;

    auto load_w = [&](int jc) {
        const int j0 = jc * 128;
        const uint32_t w1d = sb + OW1 + (jc & 1) * W1SZ;
        const uint32_t w2d = sb + OW2 + (jc & 1) * W2SZ;
        #pragma unroll
        for (int t = 0; t < 6; t++) {          // W1: 128 x 96 bf16
            int idx = tid + t * 256;
            int row = idx / 12, c16 = idx % 12;
            cp16(w1d + row * SHI + c16 * 16, W1h + (size_t)(j0 + row) * HDq + c16 * 8);
        }
        #pragma unroll
        for (int t = 0; t < 6; t++) {          // W2: 96 x 128 bf16
            int idx = tid + t * 256;
            int row = idx >> 4, c16 = idx & 15;
            cp16(w2d + row * SF + c16 * 16, W2h + (size_t)row * HIDq + j0 + c16 * 8);
        }
        CP_COMMIT();
    };

    // prologue: Hi tile + W chunk 0
    #pragma unroll
    for (int t = 0; t < 6; t++) {
        int idx = tid + t * 256;
        int row = idx / 12, c16 = idx % 12;
        cp16(sb + OHI + row * SHI + c16 * 16,
             g_Hib + (size_t)(mtile + row) * Cq + head * HDq + c16 * 8);
    }
    load_w(0);

    float acc2[2][6][4];
    #pragma unroll
    for (int a = 0; a < 2; a++)
        #pragma unroll
        for (int b = 0; b < 6; b++)
            #pragma unroll
            for (int c = 0; c < 4; c++) acc2[a][b][c] = 0.f;

    #pragma unroll 1
    for (int jc = 0; jc < 3; jc++) {
        const int j0 = jc * 128;
        CP_WAIT(0);
        __syncthreads();
        if (jc + 1 < 3) load_w(jc + 1);

        const uint32_t w1b = sb + OW1 + (jc & 1) * W1SZ;
        const uint32_t w2b = sb + OW2 + (jc & 1) * W2SZ;

        // ---- layer 1: F = relu(Hi @ W1c^T + b1) ----
        float acc1[2][8][4];
        #pragma unroll
        for (int a = 0; a < 2; a++)
            #pragma unroll
            for (int b = 0; b < 8; b++)
                #pragma unroll
                for (int c = 0; c < 4; c++) acc1[a][b][c] = 0.f;

        #pragma unroll
        for (int ks = 0; ks < 6; ks++) {       // K = 96
            uint32_t afr[2][4], bfr[4][4];
            #pragma unroll
            for (int mf = 0; mf < 2; mf++) {
                int row = wm + mf * 16 + (lane & 15);
                ldsm_x4(afr[mf], sb + OHI + row * SHI + (lane >> 4) * 16 + ks * 32);
            }
            #pragma unroll
            for (int p = 0; p < 4; p++) {
                int g = lane >> 3;
                int row = wn1 + p * 16 + (g >> 1) * 8 + (lane & 7);
                ldsm_x4(bfr[p], w1b + row * SHI + (g & 1) * 16 + ks * 32);
            }
            #pragma unroll
            for (int mf = 0; mf < 2; mf++)
                #pragma unroll
                for (int nf = 0; nf < 8; nf++)
                    mma16816(acc1[mf][nf], afr[mf], &bfr[nf >> 1][(nf & 1) * 2]);
        }

        // relu + b1, pack bf16x2 into F
        #pragma unroll
        for (int mf = 0; mf < 2; mf++) {
            const int m0 = wm + mf * 16 + (lane >> 2);
            #pragma unroll
            for (int nf = 0; nf < 8; nf++) {
                const int jl = wn1 + nf * 8 + 2 * (lane & 3);
                const float c0 = __ldg(&b1h[j0 + jl]), c1 = __ldg(&b1h[j0 + jl + 1]);
                float v0 = fmaxf(acc1[mf][nf][0] + c0, 0.f);
                float v1 = fmaxf(acc1[mf][nf][1] + c1, 0.f);
                float v2 = fmaxf(acc1[mf][nf][2] + c0, 0.f);
                float v3 = fmaxf(acc1[mf][nf][3] + c1, 0.f);
                __nv_bfloat162 p0 = __floats2bfloat162_rn(v0, v1);
                __nv_bfloat162 p1 = __floats2bfloat162_rn(v2, v3);
                *reinterpret_cast<uint32_t*>(smem + OF + m0 * SF + jl * 2) =
                    *reinterpret_cast<uint32_t*>(&p0);
                *reinterpret_cast<uint32_t*>(smem + OF + (m0 + 8) * SF + jl * 2) =
                    *reinterpret_cast<uint32_t*>(&p1);
            }
        }
        __syncthreads();

        // ---- layer 2 partial: acc2 += F @ W2c^T ----
        #pragma unroll
        for (int ks = 0; ks < 8; ks++) {       // K = 128
            uint32_t afr[2][4], bfr[3][4];
            #pragma unroll
            for (int mf = 0; mf < 2; mf++) {
                int row = wm + mf * 16 + (lane & 15);
                ldsm_x4(afr[mf], sb + OF + row * SF + (lane >> 4) * 16 + ks * 32);
            }
            #pragma unroll
            for (int p = 0; p < 3; p++) {
                int g = lane >> 3;
                int row = wn2 + p * 16 + (g >> 1) * 8 + (lane & 7);
                ldsm_x4(bfr[p], w2b + row * SF + (g & 1) * 16 + ks * 32);
            }
            #pragma unroll
            for (int mf = 0; mf < 2; mf++)
                #pragma unroll
                for (int nf = 0; nf < 6; nf++)
                    mma16816(acc2[mf][nf], afr[mf], &bfr[nf >> 1][(nf & 1) * 2]);
        }
    }

    // epilogue: logits + b2 -> g_Al fp32
    #pragma unroll
    for (int mf = 0; mf < 2; mf++) {
        const int m0 = mtile + wm + mf * 16 + (lane >> 2);
        #pragma unroll
        for (int nf = 0; nf < 6; nf++) {
            const int n = wn2 + nf * 8 + 2 * (lane & 3);
            const float c0 = __ldg(&b2h[n]), c1 = __ldg(&b2h[n + 1]);
            *reinterpret_cast<float2*>(&g_Al[(size_t)m0 * Cq + head * HDq + n]) =
                make_float2(acc2[mf][nf][0] + c0, acc2[mf][nf][1] + c1);
            *reinterpret_cast<float2*>(&g_Al[(size_t)(m0 + 8) * Cq + head * HDq + n]) =
                make_float2(acc2[mf][nf][2] + c0, acc2[mf][nf][3] + c1);
        }
    }
}

// ---------------------------------------------------------------------------
// K3: masked online softmax-pool. Grid (B, 3): each CTA owns 256 channels.
// ---------------------------------------------------------------------------
__device__ __forceinline__ float fexp(float x) {
    x = fmaxf(x, -80.f);
    float t  = x * 1.4426950408889634f;
    float fi = floorf(t);
    float f  = t - fi;
    float p  = 1.8775767e-3f;
    p = fmaf(p, f, 8.9893397e-3f);
    p = fmaf(p, f, 5.5826318e-2f);
    p = fmaf(p, f, 2.4015361e-1f);
    p = fmaf(p, f, 6.9315308e-1f);
    p = fmaf(p, f, 1.0f);
    return __int_as_float(__float_as_int(p) + (((int)fi) << 23));
}

__global__ __launch_bounds__(256) void k3_pool(
    const float* __restrict__ mask, float* __restrict__ out)
{
    const int b  = blockIdx.x;
    const int ch = blockIdx.y * 256 + threadIdx.x;
    const size_t rowbase = (size_t)b * Sq * Cq + ch;

    float m = -INFINITY, l = 0.f, a = 0.f;

    for (int s = 0; s < Sq; s++) {
        if (mask[b * Sq + s] > 0.5f) {
            size_t t = rowbase + (size_t)s * Cq;
            float x = g_Al[t], h = g_Hi[t];
            float n  = fmaxf(m, x);
            float sc = fexp(m - n), w = fexp(x - n);
            l = fmaf(l, sc, w);
            a = fmaf(a, sc, w * h);
            m = n;
        }
    }

    out[(size_t)b * Cq + ch] = a / l;
}

// ---------------------------------------------------------------------------
extern "C" void kernel_launch(void* const* d_in, const int* in_sizes, int n_in,
                              void* d_out, int out_size)
{
    const float* X    = (const float*)d_in[0];   // (B,S,D)
    const float* mask = (const float*)d_in[1];   // (B,S)
    const float* P    = (const float*)d_in[2];   // (NH,HD,D)
    const float* bP   = (const float*)d_in[3];   // (NH,HD)
    const float* W1   = (const float*)d_in[4];   // (NH,HID,HD)
    const float* b1   = (const float*)d_in[5];   // (NH,HID)
    const float* W2   = (const float*)d_in[6];   // (NH,HD,HID)
    const float* b2   = (const float*)d_in[7];   // (NH,HD)
    float* out = (float*)d_out;                  // (B, NH*HD)

    cudaFuncSetAttribute(k1_mma, cudaFuncAttributeMaxDynamicSharedMemorySize, K1_SMEM);
    cudaFuncSetAttribute(k2_mlp, cudaFuncAttributeMaxDynamicSharedMemorySize, K2_SMEM);

    __nv_bfloat16 *Xh, *Xl, *Ph, *Pl, *W1b, *W2b;
    cudaGetSymbolAddress((void**)&Xh,  g_Xh);
    cudaGetSymbolAddress((void**)&Xl,  g_Xl);
    cudaGetSymbolAddress((void**)&Ph,  g_Ph);
    cudaGetSymbolAddress((void**)&Pl,  g_Pl);
    cudaGetSymbolAddress((void**)&W1b, g_W1b);
    cudaGetSymbolAddress((void**)&W2b, g_W2b);

    // K0: bf16 splits / converts
    {
        int n4x = Mq * Dq / 4;
        k0_split<<<(n4x + 255) / 256, 256>>>(X, Xh, Xl, n4x);
        int n4p = Cq * Dq / 4;
        k0_split<<<(n4p + 255) / 256, 256>>>(P, Ph, Pl, n4p);
        int n4w = NHq * HIDq * HDq / 4;
        k0_cvt<<<(n4w + 255) / 256, 256>>>(W1, W1b, n4w);
        k0_cvt<<<(n4w + 255) / 256, 256>>>(W2, W2b, n4w);
    }

    // K1: projection GEMM (HMMA, 3-split bf16); x = N-tile for L2 reuse
    dim3 g1(Cq / 128, Mq / 128);
    k1_mma<<<g1, 256, K1_SMEM>>>(Xh, Xl, Ph, Pl, bP);

    // K2: fused MLP logits; x = head for L2 reuse of Hib
    dim3 g2(NHq, Mq / 128);
    k2_mlp<<<g2, 256, K2_SMEM>>>(b1, b2);

    // K3: masked softmax pooling, 3-way channel split
    dim3 g3(Bq, 3);
    k3_pool<<<g3, 256>>>(mask, out);
}

// round 5
// speedup vs baseline: 4.8064x; 1.1424x over previous
#include <cuda_runtime.h>
#include <cuda_bf16.h>
#include <math.h>
#include <stdint.h>

#define Bq   128
#define Sq   512
#define Dq   768
#define NHq  8
#define HDq  96
#define HIDq 384
#define Cq   768            // NH*HD
#define Mq   (Bq*Sq)        // 65536 tokens

// ---------------------------------------------------------------------------
// Scratch (__device__ globals; cudaMalloc is forbidden)
// ---------------------------------------------------------------------------
__device__ __nv_bfloat16  g_Hh [(size_t)Mq * Cq];   // 96 MB Hi high bf16
__device__ __nv_bfloat16  g_Hl [(size_t)Mq * Cq];   // 96 MB Hi low  bf16
__device__ __nv_bfloat16  g_Xh [(size_t)Mq * Dq];   // 96 MB X hi
__device__ __nv_bfloat16  g_Xl [(size_t)Mq * Dq];   // 96 MB X lo
__device__ __nv_bfloat16  g_Ph [(size_t)Cq * Dq];
__device__ __nv_bfloat16  g_Pl [(size_t)Cq * Dq];
__device__ __nv_bfloat16  g_W1b[(size_t)NHq * HIDq * HDq];
__device__ __nv_bfloat16  g_W2b[(size_t)NHq * HDq * HIDq];
__device__ float          g_part[(size_t)(Mq/128) * 3 * Cq];  // [mtile][{m,l,a}][768]

// ---------------------------------------------------------------------------
// Generic-PTX tensor-core helpers (plain sm_103 target safe)
// ---------------------------------------------------------------------------
__device__ __forceinline__ uint32_t smem_u32(const void* p) {
    uint32_t a;
    asm("{ .reg .u64 t; cvta.to.shared.u64 t, %1; cvt.u32.u64 %0, t; }"
        : "=r"(a) : "l"(p));
    return a;
}
__device__ __forceinline__ void mma16816(float* c, const uint32_t* a, const uint32_t* b) {
    asm volatile("mma.sync.aligned.m16n8k16.row.col.f32.bf16.bf16.f32 "
        "{%0,%1,%2,%3}, {%4,%5,%6,%7}, {%8,%9}, {%0,%1,%2,%3};"
        : "+f"(c[0]), "+f"(c[1]), "+f"(c[2]), "+f"(c[3])
        : "r"(a[0]), "r"(a[1]), "r"(a[2]), "r"(a[3]), "r"(b[0]), "r"(b[1]));
}
__device__ __forceinline__ void ldsm_x4(uint32_t* r, uint32_t addr) {
    asm volatile("ldmatrix.sync.aligned.m8n8.x4.shared.b16 {%0,%1,%2,%3}, [%4];"
        : "=r"(r[0]), "=r"(r[1]), "=r"(r[2]), "=r"(r[3]) : "r"(addr));
}
__device__ __forceinline__ void cp16(uint32_t dst, const void* src) {
    asm volatile("cp.async.cg.shared.global [%0], [%1], 16;" :: "r"(dst), "l"(src));
}
#define CP_COMMIT()  asm volatile("cp.async.commit_group;" ::: "memory")
#define CP_WAIT(n)   asm volatile("cp.async.wait_group %0;" :: "n"(n) : "memory")
#define SW(o)        ((o) ^ (((o) >> 3) & 0x70))

__device__ __forceinline__ float fexp(float x) {
    x = fmaxf(x, -80.f);
    float t  = x * 1.4426950408889634f;
    float fi = floorf(t);
    float f  = t - fi;
    float p  = 1.8775767e-3f;
    p = fmaf(p, f, 8.9893397e-3f);
    p = fmaf(p, f, 5.5826318e-2f);
    p = fmaf(p, f, 2.4015361e-1f);
    p = fmaf(p, f, 6.9315308e-1f);
    p = fmaf(p, f, 1.0f);
    return __int_as_float(__float_as_int(p) + (((int)fi) << 23));
}

// ---------------------------------------------------------------------------
// K0: fp32 -> bf16 hi/lo split | fp32 -> bf16 convert
// ---------------------------------------------------------------------------
__global__ __launch_bounds__(256) void k0_split(
    const float* __restrict__ src, __nv_bfloat16* __restrict__ hi,
    __nv_bfloat16* __restrict__ lo, int n4)
{
    int i = blockIdx.x * 256 + threadIdx.x;
    if (i >= n4) return;
    float4 v = reinterpret_cast<const float4*>(src)[i];
    __nv_bfloat16 h0 = __float2bfloat16(v.x), h1 = __float2bfloat16(v.y);
    __nv_bfloat16 h2 = __float2bfloat16(v.z), h3 = __float2bfloat16(v.w);
    ushort4 H, L;
    H.x = __bfloat16_as_ushort(h0); H.y = __bfloat16_as_ushort(h1);
    H.z = __bfloat16_as_ushort(h2); H.w = __bfloat16_as_ushort(h3);
    L.x = __bfloat16_as_ushort(__float2bfloat16(v.x - __bfloat162float(h0)));
    L.y = __bfloat16_as_ushort(__float2bfloat16(v.y - __bfloat162float(h1)));
    L.z = __bfloat16_as_ushort(__float2bfloat16(v.z - __bfloat162float(h2)));
    L.w = __bfloat16_as_ushort(__float2bfloat16(v.w - __bfloat162float(h3)));
    reinterpret_cast<ushort4*>(hi)[i] = H;
    reinterpret_cast<ushort4*>(lo)[i] = L;
}

__global__ __launch_bounds__(256) void k0_cvt(
    const float* __restrict__ src, __nv_bfloat16* __restrict__ dst, int n4)
{
    int i = blockIdx.x * 256 + threadIdx.x;
    if (i >= n4) return;
    float4 v = reinterpret_cast<const float4*>(src)[i];
    ushort4 H;
    H.x = __bfloat16_as_ushort(__float2bfloat16(v.x));
    H.y = __bfloat16_as_ushort(__float2bfloat16(v.y));
    H.z = __bfloat16_as_ushort(__float2bfloat16(v.z));
    H.w = __bfloat16_as_ushort(__float2bfloat16(v.w));
    reinterpret_cast<ushort4*>(dst)[i] = H;
}

// ---------------------------------------------------------------------------
// K1: HMMA bf16 3-split GEMM  Hi = X @ P^T + bP ; outputs bf16 hi/lo pair.
// ---------------------------------------------------------------------------
#define K1_STG  65536
#define K1_SMEM (3 * K1_STG)

__global__ __launch_bounds__(256) void k1_mma(
    const __nv_bfloat16* __restrict__ Xh, const __nv_bfloat16* __restrict__ Xl,
    const __nv_bfloat16* __restrict__ Ph, const __nv_bfloat16* __restrict__ Pl,
    const float* __restrict__ bP)
{
    extern __shared__ char smem[];
    const uint32_t sb = smem_u32(smem);
    const int tid  = threadIdx.x;
    const int wid  = tid >> 5, lane = tid & 31;
    const int bn   = blockIdx.x * 128, bm = blockIdx.y * 128;
    const int wm   = (wid >> 1) * 32,  wn = (wid & 1) * 64;

    float acc[2][8][4];
    #pragma unroll
    for (int a = 0; a < 2; a++)
        #pragma unroll
        for (int b = 0; b < 8; b++)
            #pragma unroll
            for (int c = 0; c < 4; c++) acc[a][b][c] = 0.f;

    auto load_chunk = [&](int c, int s) {
        const int kb = c * 64;
        const uint32_t st = sb + s * K1_STG;
        #pragma unroll
        for (int t = 0; t < 4; t++) {
            int idx = tid + t * 256;
            int row = idx >> 3, c16 = idx & 7;
            uint32_t off = SW(row * 128 + c16 * 16);
            const size_t gx = (size_t)(bm + row) * Dq + kb + c16 * 8;
            const size_t gp = (size_t)(bn + row) * Dq + kb + c16 * 8;
            cp16(st +         off, Xh + gx);
            cp16(st + 16384 + off, Xl + gx);
            cp16(st + 32768 + off, Ph + gp);
            cp16(st + 49152 + off, Pl + gp);
        }
        CP_COMMIT();
    };

    load_chunk(0, 0);
    load_chunk(1, 1);

    #pragma unroll 1
    for (int c = 0; c < 12; c++) {
        if (c < 10) { CP_WAIT(1); } else { CP_WAIT(0); }
        __syncthreads();
        if (c + 2 < 12) load_chunk(c + 2, (c + 2) % 3);

        const uint32_t st  = sb + (c % 3) * K1_STG;
        const uint32_t sAh = st, sAl = st + 16384, sBh = st + 32768, sBl = st + 49152;
        #pragma unroll
        for (int ks = 0; ks < 4; ks++) {
            uint32_t ah[2][4], al[2][4], bh[4][4], bl[4][4];
            #pragma unroll
            for (int mf = 0; mf < 2; mf++) {
                int row = wm + mf * 16 + (lane & 15);
                uint32_t off = SW(row * 128 + ((lane >> 4) + ks * 2) * 16);
                ldsm_x4(ah[mf], sAh + off);
                ldsm_x4(al[mf], sAl + off);
            }
            #pragma unroll
            for (int p = 0; p < 4; p++) {
                int g = lane >> 3;
                int row = wn + p * 16 + (g >> 1) * 8 + (lane & 7);
                uint32_t off = SW(row * 128 + (ks * 2 + (g & 1)) * 16);
                ldsm_x4(bh[p], sBh + off);
                ldsm_x4(bl[p], sBl + off);
            }
            #pragma unroll
            for (int mf = 0; mf < 2; mf++)
                #pragma unroll
                for (int nf = 0; nf < 8; nf++) {
                    mma16816(acc[mf][nf], ah[mf], &bh[nf >> 1][(nf & 1) * 2]);
                    mma16816(acc[mf][nf], ah[mf], &bl[nf >> 1][(nf & 1) * 2]);
                    mma16816(acc[mf][nf], al[mf], &bh[nf >> 1][(nf & 1) * 2]);
                }
        }
    }

    // epilogue: v = D + bias -> bf16 hi/lo pair
    #pragma unroll
    for (int mf = 0; mf < 2; mf++) {
        const int m0 = bm + wm + mf * 16 + (lane >> 2);
        #pragma unroll
        for (int nf = 0; nf < 8; nf++) {
            const int n = bn + wn + nf * 8 + 2 * (lane & 3);
            const float b0 = __ldg(&bP[n]), b1 = __ldg(&bP[n + 1]);
            float v[4] = { acc[mf][nf][0] + b0, acc[mf][nf][1] + b1,
                           acc[mf][nf][2] + b0, acc[mf][nf][3] + b1 };
            __nv_bfloat16 h[4], l[4];
            #pragma unroll
            for (int q = 0; q < 4; q++) {
                h[q] = __float2bfloat16(v[q]);
                l[q] = __float2bfloat16(v[q] - __bfloat162float(h[q]));
            }
            *reinterpret_cast<__nv_bfloat162*>(&g_Hh[(size_t)m0 * Cq + n]) =
                __nv_bfloat162(h[0], h[1]);
            *reinterpret_cast<__nv_bfloat162*>(&g_Hh[(size_t)(m0 + 8) * Cq + n]) =
                __nv_bfloat162(h[2], h[3]);
            *reinterpret_cast<__nv_bfloat162*>(&g_Hl[(size_t)m0 * Cq + n]) =
                __nv_bfloat162(l[0], l[1]);
            *reinterpret_cast<__nv_bfloat162*>(&g_Hl[(size_t)(m0 + 8) * Cq + n]) =
                __nv_bfloat162(l[2], l[3]);
        }
    }
}

// ---------------------------------------------------------------------------
// K2: fused MLP + partial masked softmax-pool.
// CTA = (head, 128-token tile). Logits never leave the CTA; writes per-CTA
// online-softmax partials (m, l, a[96]) to g_part.
// smem: Hh@0 (26624), Hl@26624 (26624), F@53248 (34816),
//       W1 dbuf@88064 (53248; reused as fp32 logits A[128][96] post-loop),
//       W2 dbuf@141312 (52224; reused as reduction scratch). Total 193536.
// ---------------------------------------------------------------------------
#define OHH  0
#define OHL  26624
#define OF   53248
#define OW1  88064
#define OW2  141312
#define W1SZ 26624
#define W2SZ 26112
#define K2_SMEM 193536
#define SHI  208
#define SF   272

__global__ __launch_bounds__(256, 1) void k2_fused(
    const float* __restrict__ b1, const float* __restrict__ b2,
    const float* __restrict__ mask)
{
    extern __shared__ char smem[];
    const uint32_t sb = smem_u32(smem);
    const int tid = threadIdx.x, wid = tid >> 5, lane = tid & 31;
    const int head  = blockIdx.x;
    const int mt    = blockIdx.y;            // 0..511
    const int mtile = mt * 128;
    const int batch = mt >> 2;
    const int soff  = (mt & 3) * 128;
    const int wm  = (wid >> 1) * 32;
    const int wn1 = (wid & 1) * 64;
    const int wn2 = (wid & 1) * 48;

    const __nv_bfloat16* W1h = g_W1b + (size_t)head * HIDq * HDq;
    const __nv_bfloat16* W2h = g_W2b + (size_t)head * HDq * HIDq;
    const float* b1h = b1 + head * HIDq;
    const float* b2h = b2 + head * HDq;

    auto load_w = [&](int jc) {
        const int j0 = jc * 128;
        const uint32_t w1d = sb + OW1 + (jc & 1) * W1SZ;
        const uint32_t w2d = sb + OW2 + (jc & 1) * W2SZ;
        #pragma unroll
        for (int t = 0; t < 6; t++) {
            int idx = tid + t * 256;
            int row = idx / 12, c16 = idx % 12;
            cp16(w1d + row * SHI + c16 * 16, W1h + (size_t)(j0 + row) * HDq + c16 * 8);
        }
        #pragma unroll
        for (int t = 0; t < 6; t++) {
            int idx = tid + t * 256;
            int row = idx >> 4, c16 = idx & 15;
            cp16(w2d + row * SF + c16 * 16, W2h + (size_t)row * HIDq + j0 + c16 * 8);
        }
        CP_COMMIT();
    };

    // prologue: Hh + Hl tiles + W chunk 0
    #pragma unroll
    for (int t = 0; t < 6; t++) {
        int idx = tid + t * 256;
        int row = idx / 12, c16 = idx % 12;
        const size_t g = (size_t)(mtile + row) * Cq + head * HDq + c16 * 8;
        cp16(sb + OHH + row * SHI + c16 * 16, g_Hh + g);
        cp16(sb + OHL + row * SHI + c16 * 16, g_Hl + g);
    }
    load_w(0);

    float acc2[2][6][4];
    #pragma unroll
    for (int a = 0; a < 2; a++)
        #pragma unroll
        for (int b = 0; b < 6; b++)
            #pragma unroll
            for (int c = 0; c < 4; c++) acc2[a][b][c] = 0.f;

    #pragma unroll 1
    for (int jc = 0; jc < 3; jc++) {
        const int j0 = jc * 128;
        CP_WAIT(0);
        __syncthreads();
        if (jc + 1 < 3) load_w(jc + 1);

        const uint32_t w1b = sb + OW1 + (jc & 1) * W1SZ;
        const uint32_t w2b = sb + OW2 + (jc & 1) * W2SZ;

        float acc1[2][8][4];
        #pragma unroll
        for (int a = 0; a < 2; a++)
            #pragma unroll
            for (int b = 0; b < 8; b++)
                #pragma unroll
                for (int c = 0; c < 4; c++) acc1[a][b][c] = 0.f;

        #pragma unroll
        for (int ks = 0; ks < 6; ks++) {       // K = 96
            uint32_t afr[2][4], bfr[4][4];
            #pragma unroll
            for (int mf = 0; mf < 2; mf++) {
                int row = wm + mf * 16 + (lane & 15);
                ldsm_x4(afr[mf], sb + OHH + row * SHI + (lane >> 4) * 16 + ks * 32);
            }
            #pragma unroll
            for (int p = 0; p < 4; p++) {
                int g = lane >> 3;
                int row = wn1 + p * 16 + (g >> 1) * 8 + (lane & 7);
                ldsm_x4(bfr[p], w1b + row * SHI + (g & 1) * 16 + ks * 32);
            }
            #pragma unroll
            for (int mf = 0; mf < 2; mf++)
                #pragma unroll
                for (int nf = 0; nf < 8; nf++)
                    mma16816(acc1[mf][nf], afr[mf], &bfr[nf >> 1][(nf & 1) * 2]);
        }

        // relu + b1 -> F (bf16)
        #pragma unroll
        for (int mf = 0; mf < 2; mf++) {
            const int m0 = wm + mf * 16 + (lane >> 2);
            #pragma unroll
            for (int nf = 0; nf < 8; nf++) {
                const int jl = wn1 + nf * 8 + 2 * (lane & 3);
                const float c0 = __ldg(&b1h[j0 + jl]), c1 = __ldg(&b1h[j0 + jl + 1]);
                float v0 = fmaxf(acc1[mf][nf][0] + c0, 0.f);
                float v1 = fmaxf(acc1[mf][nf][1] + c1, 0.f);
                float v2 = fmaxf(acc1[mf][nf][2] + c0, 0.f);
                float v3 = fmaxf(acc1[mf][nf][3] + c1, 0.f);
                __nv_bfloat162 p0 = __floats2bfloat162_rn(v0, v1);
                __nv_bfloat162 p1 = __floats2bfloat162_rn(v2, v3);
                *reinterpret_cast<uint32_t*>(smem + OF + m0 * SF + jl * 2) =
                    *reinterpret_cast<uint32_t*>(&p0);
                *reinterpret_cast<uint32_t*>(smem + OF + (m0 + 8) * SF + jl * 2) =
                    *reinterpret_cast<uint32_t*>(&p1);
            }
        }
        __syncthreads();

        #pragma unroll
        for (int ks = 0; ks < 8; ks++) {       // K = 128
            uint32_t afr[2][4], bfr[3][4];
            #pragma unroll
            for (int mf = 0; mf < 2; mf++) {
                int row = wm + mf * 16 + (lane & 15);
                ldsm_x4(afr[mf], sb + OF + row * SF + (lane >> 4) * 16 + ks * 32);
            }
            #pragma unroll
            for (int p = 0; p < 3; p++) {
                int g = lane >> 3;
                int row = wn2 + p * 16 + (g >> 1) * 8 + (lane & 7);
                ldsm_x4(bfr[p], w2b + row * SF + (g & 1) * 16 + ks * 32);
            }
            #pragma unroll
            for (int mf = 0; mf < 2; mf++)
                #pragma unroll
                for (int nf = 0; nf < 6; nf++)
                    mma16816(acc2[mf][nf], afr[mf], &bfr[nf >> 1][(nf & 1) * 2]);
        }
    }

    // ---- logits (+b2) -> smem A (fp32, [128][96], reuses W1 dbuf region) ----
    __syncthreads();
    float* As = reinterpret_cast<float*>(smem + OW1);
    float* mk = reinterpret_cast<float*>(smem + OF);          // 128 floats
    #pragma unroll
    for (int mf = 0; mf < 2; mf++) {
        const int m0 = wm + mf * 16 + (lane >> 2);
        #pragma unroll
        for (int nf = 0; nf < 6; nf++) {
            const int n = wn2 + nf * 8 + 2 * (lane & 3);
            const float c0 = __ldg(&b2h[n]), c1 = __ldg(&b2h[n + 1]);
            As[m0 * 96 + n]           = acc2[mf][nf][0] + c0;
            As[m0 * 96 + n + 1]       = acc2[mf][nf][1] + c1;
            As[(m0 + 8) * 96 + n]     = acc2[mf][nf][2] + c0;
            As[(m0 + 8) * 96 + n + 1] = acc2[mf][nf][3] + c1;
        }
    }
    if (tid < 128) mk[tid] = mask[batch * Sq + soff + tid];
    __syncthreads();

    // ---- per-channel masked online softmax-pool over 128 tokens ----
    float* red = reinterpret_cast<float*>(smem + OW2);        // [2][3][96]
    if (tid < 192) {
        const int ch = tid % 96, half = tid / 96;
        float m = -1e30f, l = 0.f, a = 0.f;
        for (int t = half * 64; t < half * 64 + 64; t++) {
            if (mk[t] > 0.5f) {
                float x  = As[t * 96 + ch];
                float hv = __bfloat162float(*reinterpret_cast<__nv_bfloat16*>(
                               smem + OHH + t * SHI + ch * 2))
                         + __bfloat162float(*reinterpret_cast<__nv_bfloat16*>(
                               smem + OHL + t * SHI + ch * 2));
                float n  = fmaxf(m, x);
                float sc = fexp(m - n), w = fexp(x - n);
                l = fmaf(l, sc, w);
                a = fmaf(a, sc, w * hv);
                m = n;
            }
        }
        red[(half * 3 + 0) * 96 + ch] = m;
        red[(half * 3 + 1) * 96 + ch] = l;
        red[(half * 3 + 2) * 96 + ch] = a;
    }
    __syncthreads();
    if (tid < 96) {
        const int ch = tid;
        float m0 = red[0 * 96 + ch], l0 = red[1 * 96 + ch], a0 = red[2 * 96 + ch];
        float m1 = red[3 * 96 + ch], l1 = red[4 * 96 + ch], a1 = red[5 * 96 + ch];
        float n  = fmaxf(fmaxf(m0, m1), -1e30f);
        float s0 = fexp(m0 - n), s1 = fexp(m1 - n);
        float l  = l0 * s0 + l1 * s1;
        float a  = a0 * s0 + a1 * s1;
        float* dst = &g_part[(size_t)mt * 3 * Cq + head * HDq + ch];
        dst[0]       = n;
        dst[Cq]      = l;
        dst[2 * Cq]  = a;
    }
}

// ---------------------------------------------------------------------------
// K3: merge 4 chunk partials per (batch, channel) -> output
// ---------------------------------------------------------------------------
__global__ __launch_bounds__(256) void k3_reduce(float* __restrict__ out)
{
    const int idx = blockIdx.x * 256 + threadIdx.x;   // 0..98303
    const int b = idx / Cq, ch = idx % Cq;

    float m = -1e30f;
    #pragma unroll
    for (int c = 0; c < 4; c++)
        m = fmaxf(m, g_part[(size_t)(b * 4 + c) * 3 * Cq + ch]);

    float l = 0.f, a = 0.f;
    #pragma unroll
    for (int c = 0; c < 4; c++) {
        const float* p = &g_part[(size_t)(b * 4 + c) * 3 * Cq + ch];
        float s = fexp(p[0] - m);
        l = fmaf(p[Cq],     s, l);
        a = fmaf(p[2 * Cq], s, a);
    }
    out[idx] = a / l;
}

// ---------------------------------------------------------------------------
extern "C" void kernel_launch(void* const* d_in, const int* in_sizes, int n_in,
                              void* d_out, int out_size)
{
    const float* X    = (const float*)d_in[0];
    const float* mask = (const float*)d_in[1];
    const float* P    = (const float*)d_in[2];
    const float* bP   = (const float*)d_in[3];
    const float* W1   = (const float*)d_in[4];
    const float* b1   = (const float*)d_in[5];
    const float* W2   = (const float*)d_in[6];
    const float* b2   = (const float*)d_in[7];
    float* out = (float*)d_out;

    cudaFuncSetAttribute(k1_mma,   cudaFuncAttributeMaxDynamicSharedMemorySize, K1_SMEM);
    cudaFuncSetAttribute(k2_fused, cudaFuncAttributeMaxDynamicSharedMemorySize, K2_SMEM);

    __nv_bfloat16 *Xh, *Xl, *Ph, *Pl, *W1b, *W2b;
    cudaGetSymbolAddress((void**)&Xh,  g_Xh);
    cudaGetSymbolAddress((void**)&Xl,  g_Xl);
    cudaGetSymbolAddress((void**)&Ph,  g_Ph);
    cudaGetSymbolAddress((void**)&Pl,  g_Pl);
    cudaGetSymbolAddress((void**)&W1b, g_W1b);
    cudaGetSymbolAddress((void**)&W2b, g_W2b);

    // K0: bf16 splits / converts
    {
        int n4x = Mq * Dq / 4;
        k0_split<<<(n4x + 255) / 256, 256>>>(X, Xh, Xl, n4x);
        int n4p = Cq * Dq / 4;
        k0_split<<<(n4p + 255) / 256, 256>>>(P, Ph, Pl, n4p);
        int n4w = NHq * HIDq * HDq / 4;
        k0_cvt<<<(n4w + 255) / 256, 256>>>(W1, W1b, n4w);
        k0_cvt<<<(n4w + 255) / 256, 256>>>(W2, W2b, n4w);
    }

    // K1: projection GEMM (x = N-tile fast for L2 reuse of X)
    dim3 g1(Cq / 128, Mq / 128);
    k1_mma<<<g1, 256, K1_SMEM>>>(Xh, Xl, Ph, Pl, bP);

    // K2: fused MLP + partial softmax-pool (x = head fast for L2 reuse of Hi)
    dim3 g2(NHq, Mq / 128);
    k2_fused<<<g2, 256, K2_SMEM>>>(b1, b2, mask);

    // K3: merge partials
    k3_reduce<<<(Bq * Cq) / 256, 256>>>(out);
}

// round 6
// speedup vs baseline: 5.3003x; 1.1028x over previous
#include <cuda_runtime.h>
#include <cuda_bf16.h>
#include <math.h>
#include <stdint.h>

#define Bq   128
#define Sq   512
#define Dq   768
#define NHq  8
#define HDq  96
#define HIDq 384
#define Cq   768            // NH*HD
#define Mq   (Bq*Sq)        // 65536 tokens

// ---------------------------------------------------------------------------
// Scratch (__device__ globals; cudaMalloc is forbidden)
// ---------------------------------------------------------------------------
__device__ __nv_bfloat16  g_Xh [(size_t)Mq * Dq];   // 96 MB X hi
__device__ __nv_bfloat16  g_Xl [(size_t)Mq * Dq];   // 96 MB X lo
__device__ __nv_bfloat16  g_Ph [(size_t)Cq * Dq];
__device__ __nv_bfloat16  g_Pl [(size_t)Cq * Dq];
__device__ __nv_bfloat16  g_W1b[(size_t)NHq * HIDq * HDq];
__device__ __nv_bfloat16  g_W2b[(size_t)NHq * HDq * HIDq];
__device__ float          g_part[(size_t)(Mq/128) * 3 * Cq];  // [mtile][{m,l,a}][768]

// ---------------------------------------------------------------------------
// Generic-PTX tensor-core helpers (plain sm_103 target safe)
// ---------------------------------------------------------------------------
__device__ __forceinline__ uint32_t smem_u32(const void* p) {
    uint32_t a;
    asm("{ .reg .u64 t; cvta.to.shared.u64 t, %1; cvt.u32.u64 %0, t; }"
        : "=r"(a) : "l"(p));
    return a;
}
__device__ __forceinline__ void mma16816(float* c, const uint32_t* a, const uint32_t* b) {
    asm volatile("mma.sync.aligned.m16n8k16.row.col.f32.bf16.bf16.f32 "
        "{%0,%1,%2,%3}, {%4,%5,%6,%7}, {%8,%9}, {%0,%1,%2,%3};"
        : "+f"(c[0]), "+f"(c[1]), "+f"(c[2]), "+f"(c[3])
        : "r"(a[0]), "r"(a[1]), "r"(a[2]), "r"(a[3]), "r"(b[0]), "r"(b[1]));
}
__device__ __forceinline__ void ldsm_x4(uint32_t* r, uint32_t addr) {
    asm volatile("ldmatrix.sync.aligned.m8n8.x4.shared.b16 {%0,%1,%2,%3}, [%4];"
        : "=r"(r[0]), "=r"(r[1]), "=r"(r[2]), "=r"(r[3]) : "r"(addr));
}
__device__ __forceinline__ void cp16(uint32_t dst, const void* src) {
    asm volatile("cp.async.cg.shared.global [%0], [%1], 16;" :: "r"(dst), "l"(src));
}
#define CP_COMMIT()  asm volatile("cp.async.commit_group;" ::: "memory")
#define CP_WAIT(n)   asm volatile("cp.async.wait_group %0;" :: "n"(n) : "memory")
#define SW(o)        ((o) ^ (((o) >> 3) & 0x70))

__device__ __forceinline__ float fexp(float x) {
    x = fmaxf(x, -80.f);
    float t  = x * 1.4426950408889634f;
    float fi = floorf(t);
    float f  = t - fi;
    float p  = 1.8775767e-3f;
    p = fmaf(p, f, 8.9893397e-3f);
    p = fmaf(p, f, 5.5826318e-2f);
    p = fmaf(p, f, 2.4015361e-1f);
    p = fmaf(p, f, 6.9315308e-1f);
    p = fmaf(p, f, 1.0f);
    return __int_as_float(__float_as_int(p) + (((int)fi) << 23));
}

// ---------------------------------------------------------------------------
// K0: fp32 -> bf16 hi/lo split | fp32 -> bf16 convert
// ---------------------------------------------------------------------------
__global__ __launch_bounds__(256) void k0_split(
    const float* __restrict__ src, __nv_bfloat16* __restrict__ hi,
    __nv_bfloat16* __restrict__ lo, int n4)
{
    int i = blockIdx.x * 256 + threadIdx.x;
    if (i >= n4) return;
    float4 v = reinterpret_cast<const float4*>(src)[i];
    __nv_bfloat16 h0 = __float2bfloat16(v.x), h1 = __float2bfloat16(v.y);
    __nv_bfloat16 h2 = __float2bfloat16(v.z), h3 = __float2bfloat16(v.w);
    ushort4 H, L;
    H.x = __bfloat16_as_ushort(h0); H.y = __bfloat16_as_ushort(h1);
    H.z = __bfloat16_as_ushort(h2); H.w = __bfloat16_as_ushort(h3);
    L.x = __bfloat16_as_ushort(__float2bfloat16(v.x - __bfloat162float(h0)));
    L.y = __bfloat16_as_ushort(__float2bfloat16(v.y - __bfloat162float(h1)));
    L.z = __bfloat16_as_ushort(__float2bfloat16(v.z - __bfloat162float(h2)));
    L.w = __bfloat16_as_ushort(__float2bfloat16(v.w - __bfloat162float(h3)));
    reinterpret_cast<ushort4*>(hi)[i] = H;
    reinterpret_cast<ushort4*>(lo)[i] = L;
}

__global__ __launch_bounds__(256) void k0_cvt(
    const float* __restrict__ src, __nv_bfloat16* __restrict__ dst, int n4)
{
    int i = blockIdx.x * 256 + threadIdx.x;
    if (i >= n4) return;
    float4 v = reinterpret_cast<const float4*>(src)[i];
    ushort4 H;
    H.x = __bfloat16_as_ushort(__float2bfloat16(v.x));
    H.y = __bfloat16_as_ushort(__float2bfloat16(v.y));
    H.z = __bfloat16_as_ushort(__float2bfloat16(v.z));
    H.w = __bfloat16_as_ushort(__float2bfloat16(v.w));
    reinterpret_cast<ushort4*>(dst)[i] = H;
}

// ---------------------------------------------------------------------------
// KF: fully fused per-(head, 128-token tile) kernel.
//   Phase A: Hi[128x96] = X[128x768] @ P_h^T (3-term bf16 split) + bP
//            K streamed in 12 chunks of 64, double-buffered cp.async.
//   Phase B: logits = W2(relu(W1(Hi)+b1))+b2 on HMMA (3 hidden chunks of 128)
//   Phase C: in-CTA masked online-softmax partials (m, l, a[96]) -> g_part.
// smem map (bytes):
//   OHH 0      : Hi bf16 [128][208]           26624
//   OAS 26624  : Hi fp32 [128][97]            49664
//   OMK 76288  : mask     [128]                 512
//   ORD 76800  : reduce   [2][3][96] fp32      2304
//   OST 79104  : phase A: 2 stages x 57344 (Xh|Xl|Ph|Pl)   -> 193792
//                phase B: F[128][272] @OST, W1 dbuf @+34816,
//                         W2 dbuf @+88064; logits reuse W1 dbuf.
// ---------------------------------------------------------------------------
#define OHH   0
#define OAS   26624
#define OMK   76288
#define ORD   76800
#define OST   79104
#define ASTG  57344          // phase A stage: Xh 16384 | Xl 16384 | Ph 12288 | Pl 12288
#define OF    OST
#define OW1   (OST + 34816)
#define OW2   (OST + 88064)
#define W1SZ  26624
#define W2SZ  26112
#define KF_SMEM 219392
#define SHI   208
#define SF    272

__global__ __launch_bounds__(256, 1) void kf_fused(
    const __nv_bfloat16* __restrict__ Xh, const __nv_bfloat16* __restrict__ Xl,
    const __nv_bfloat16* __restrict__ Ph, const __nv_bfloat16* __restrict__ Pl,
    const float* __restrict__ bP,
    const float* __restrict__ b1, const float* __restrict__ b2,
    const float* __restrict__ mask)
{
    extern __shared__ char smem[];
    const uint32_t sb = smem_u32(smem);
    const int tid = threadIdx.x, wid = tid >> 5, lane = tid & 31;
    const int head  = blockIdx.x;
    const int mt    = blockIdx.y;
    const int mtile = mt * 128;
    const int batch = mt >> 2;
    const int soff  = (mt & 3) * 128;
    const int wm  = (wid >> 1) * 32;
    const int wnA = (wid & 1) * 48;    // phase A / layer2 N split (96 -> 2x48)
    const int wn1 = (wid & 1) * 64;    // layer1 N split (128 -> 2x64)

    const __nv_bfloat16* W1h = g_W1b + (size_t)head * HIDq * HDq;
    const __nv_bfloat16* W2h = g_W2b + (size_t)head * HDq * HIDq;
    const float* b1h = b1 + head * HIDq;
    const float* b2h = b2 + head * HDq;

    // ======================= Phase A: projection GEMM ======================
    auto load_chunk = [&](int c, int s) {
        const int kb = c * 64;
        const uint32_t st = sb + OST + s * ASTG;
        #pragma unroll
        for (int t = 0; t < 4; t++) {              // X: 128 rows x 8 col16
            int idx = tid + t * 256;
            int row = idx >> 3, c16 = idx & 7;
            uint32_t off = SW(row * 128 + c16 * 16);
            const size_t gx = (size_t)(mtile + row) * Dq + kb + c16 * 8;
            cp16(st +         off, Xh + gx);
            cp16(st + 16384 + off, Xl + gx);
        }
        #pragma unroll
        for (int t = 0; t < 3; t++) {              // P: 96 rows x 8 col16
            int idx = tid + t * 256;
            int row = idx >> 3, c16 = idx & 7;
            uint32_t off = SW(row * 128 + c16 * 16);
            const size_t gp = (size_t)(head * HDq + row) * Dq + kb + c16 * 8;
            cp16(st + 32768 + off, Ph + gp);
            cp16(st + 45056 + off, Pl + gp);
        }
        CP_COMMIT();
    };

    float accA[2][6][4];
    #pragma unroll
    for (int a = 0; a < 2; a++)
        #pragma unroll
        for (int b = 0; b < 6; b++)
            #pragma unroll
            for (int c = 0; c < 4; c++) accA[a][b][c] = 0.f;

    load_chunk(0, 0);
    #pragma unroll 1
    for (int c = 0; c < 12; c++) {
        if (c + 1 < 12) { load_chunk(c + 1, (c + 1) & 1); CP_WAIT(1); }
        else            { CP_WAIT(0); }
        __syncthreads();

        const uint32_t st  = sb + OST + (c & 1) * ASTG;
        const uint32_t sXh = st, sXl = st + 16384, sPh = st + 32768, sPl = st + 45056;
        #pragma unroll
        for (int ks = 0; ks < 4; ks++) {
            uint32_t ah[2][4], al[2][4], bh[3][4], bl[3][4];
            #pragma unroll
            for (int mf = 0; mf < 2; mf++) {
                int row = wm + mf * 16 + (lane & 15);
                uint32_t off = SW(row * 128 + ((lane >> 4) + ks * 2) * 16);
                ldsm_x4(ah[mf], sXh + off);
                ldsm_x4(al[mf], sXl + off);
            }
            #pragma unroll
            for (int p = 0; p < 3; p++) {
                int g = lane >> 3;
                int row = wnA + p * 16 + (g >> 1) * 8 + (lane & 7);
                uint32_t off = SW(row * 128 + (ks * 2 + (g & 1)) * 16);
                ldsm_x4(bh[p], sPh + off);
                ldsm_x4(bl[p], sPl + off);
            }
            #pragma unroll
            for (int mf = 0; mf < 2; mf++)
                #pragma unroll
                for (int nf = 0; nf < 6; nf++) {
                    mma16816(accA[mf][nf], ah[mf], &bh[nf >> 1][(nf & 1) * 2]);
                    mma16816(accA[mf][nf], ah[mf], &bl[nf >> 1][(nf & 1) * 2]);
                    mma16816(accA[mf][nf], al[mf], &bh[nf >> 1][(nf & 1) * 2]);
                }
        }
        __syncthreads();      // all MMAs on this stage done before overwrite
    }

    // W chunk 0 prefetch (stage buffers dead now; W dbuf overlaps them)
    auto load_w = [&](int jc) {
        const int j0 = jc * 128;
        const uint32_t w1d = sb + OW1 + (jc & 1) * W1SZ;
        const uint32_t w2d = sb + OW2 + (jc & 1) * W2SZ;
        #pragma unroll
        for (int t = 0; t < 6; t++) {
            int idx = tid + t * 256;
            int row = idx / 12, c16 = idx % 12;
            cp16(w1d + row * SHI + c16 * 16, W1h + (size_t)(j0 + row) * HDq + c16 * 8);
        }
        #pragma unroll
        for (int t = 0; t < 6; t++) {
            int idx = tid + t * 256;
            int row = idx >> 4, c16 = idx & 15;
            cp16(w2d + row * SF + c16 * 16, W2h + (size_t)row * HIDq + j0 + c16 * 8);
        }
        CP_COMMIT();
    };
    load_w(0);

    // Phase A epilogue: accA + bias -> Hi bf16 (OHH) and Hi fp32 (OAS)
    float* As = reinterpret_cast<float*>(smem + OAS);
    float* mk = reinterpret_cast<float*>(smem + OMK);
    #pragma unroll
    for (int mf = 0; mf < 2; mf++) {
        const int m0 = wm + mf * 16 + (lane >> 2);
        #pragma unroll
        for (int nf = 0; nf < 6; nf++) {
            const int n = wnA + nf * 8 + 2 * (lane & 3);
            const float c0 = __ldg(&bP[head * HDq + n]);
            const float c1 = __ldg(&bP[head * HDq + n + 1]);
            float v0 = accA[mf][nf][0] + c0, v1 = accA[mf][nf][1] + c1;
            float v2 = accA[mf][nf][2] + c0, v3 = accA[mf][nf][3] + c1;
            __nv_bfloat162 p0 = __floats2bfloat162_rn(v0, v1);
            __nv_bfloat162 p1 = __floats2bfloat162_rn(v2, v3);
            *reinterpret_cast<uint32_t*>(smem + OHH + m0 * SHI + n * 2) =
                *reinterpret_cast<uint32_t*>(&p0);
            *reinterpret_cast<uint32_t*>(smem + OHH + (m0 + 8) * SHI + n * 2) =
                *reinterpret_cast<uint32_t*>(&p1);
            As[m0 * 97 + n]           = v0;
            As[m0 * 97 + n + 1]       = v1;
            As[(m0 + 8) * 97 + n]     = v2;
            As[(m0 + 8) * 97 + n + 1] = v3;
        }
    }
    if (tid < 128) mk[tid] = mask[batch * Sq + soff + tid];
    __syncthreads();

    // ========================== Phase B: MLP ===============================
    float acc2[2][6][4];
    #pragma unroll
    for (int a = 0; a < 2; a++)
        #pragma unroll
        for (int b = 0; b < 6; b++)
            #pragma unroll
            for (int c = 0; c < 4; c++) acc2[a][b][c] = 0.f;

    #pragma unroll 1
    for (int jc = 0; jc < 3; jc++) {
        const int j0 = jc * 128;
        CP_WAIT(0);
        __syncthreads();
        if (jc + 1 < 3) load_w(jc + 1);

        const uint32_t w1b = sb + OW1 + (jc & 1) * W1SZ;
        const uint32_t w2b = sb + OW2 + (jc & 1) * W2SZ;

        float acc1[2][8][4];
        #pragma unroll
        for (int a = 0; a < 2; a++)
            #pragma unroll
            for (int b = 0; b < 8; b++)
                #pragma unroll
                for (int c = 0; c < 4; c++) acc1[a][b][c] = 0.f;

        #pragma unroll
        for (int ks = 0; ks < 6; ks++) {       // K = 96
            uint32_t afr[2][4], bfr[4][4];
            #pragma unroll
            for (int mf = 0; mf < 2; mf++) {
                int row = wm + mf * 16 + (lane & 15);
                ldsm_x4(afr[mf], sb + OHH + row * SHI + (lane >> 4) * 16 + ks * 32);
            }
            #pragma unroll
            for (int p = 0; p < 4; p++) {
                int g = lane >> 3;
                int row = wn1 + p * 16 + (g >> 1) * 8 + (lane & 7);
                ldsm_x4(bfr[p], w1b + row * SHI + (g & 1) * 16 + ks * 32);
            }
            #pragma unroll
            for (int mf = 0; mf < 2; mf++)
                #pragma unroll
                for (int nf = 0; nf < 8; nf++)
                    mma16816(acc1[mf][nf], afr[mf], &bfr[nf >> 1][(nf & 1) * 2]);
        }

        // relu + b1 -> F (bf16)
        #pragma unroll
        for (int mf = 0; mf < 2; mf++) {
            const int m0 = wm + mf * 16 + (lane >> 2);
            #pragma unroll
            for (int nf = 0; nf < 8; nf++) {
                const int jl = wn1 + nf * 8 + 2 * (lane & 3);
                const float c0 = __ldg(&b1h[j0 + jl]), c1 = __ldg(&b1h[j0 + jl + 1]);
                float v0 = fmaxf(acc1[mf][nf][0] + c0, 0.f);
                float v1 = fmaxf(acc1[mf][nf][1] + c1, 0.f);
                float v2 = fmaxf(acc1[mf][nf][2] + c0, 0.f);
                float v3 = fmaxf(acc1[mf][nf][3] + c1, 0.f);
                __nv_bfloat162 p0 = __floats2bfloat162_rn(v0, v1);
                __nv_bfloat162 p1 = __floats2bfloat162_rn(v2, v3);
                *reinterpret_cast<uint32_t*>(smem + OF + m0 * SF + jl * 2) =
                    *reinterpret_cast<uint32_t*>(&p0);
                *reinterpret_cast<uint32_t*>(smem + OF + (m0 + 8) * SF + jl * 2) =
                    *reinterpret_cast<uint32_t*>(&p1);
            }
        }
        __syncthreads();

        #pragma unroll
        for (int ks = 0; ks < 8; ks++) {       // K = 128
            uint32_t afr[2][4], bfr[3][4];
            #pragma unroll
            for (int mf = 0; mf < 2; mf++) {
                int row = wm + mf * 16 + (lane & 15);
                ldsm_x4(afr[mf], sb + OF + row * SF + (lane >> 4) * 16 + ks * 32);
            }
            #pragma unroll
            for (int p = 0; p < 3; p++) {
                int g = lane >> 3;
                int row = wnA + p * 16 + (g >> 1) * 8 + (lane & 7);
                ldsm_x4(bfr[p], w2b + row * SF + (g & 1) * 16 + ks * 32);
            }
            #pragma unroll
            for (int mf = 0; mf < 2; mf++)
                #pragma unroll
                for (int nf = 0; nf < 6; nf++)
                    mma16816(acc2[mf][nf], afr[mf], &bfr[nf >> 1][(nf & 1) * 2]);
        }
    }

    // ===================== Phase C: softmax-pool partials ==================
    __syncthreads();                            // last layer2 MMAs done
    float* Lg = reinterpret_cast<float*>(smem + OW1);   // logits [128][97]
    #pragma unroll
    for (int mf = 0; mf < 2; mf++) {
        const int m0 = wm + mf * 16 + (lane >> 2);
        #pragma unroll
        for (int nf = 0; nf < 6; nf++) {
            const int n = wnA + nf * 8 + 2 * (lane & 3);
            const float c0 = __ldg(&b2h[n]), c1 = __ldg(&b2h[n + 1]);
            Lg[m0 * 97 + n]           = acc2[mf][nf][0] + c0;
            Lg[m0 * 97 + n + 1]       = acc2[mf][nf][1] + c1;
            Lg[(m0 + 8) * 97 + n]     = acc2[mf][nf][2] + c0;
            Lg[(m0 + 8) * 97 + n + 1] = acc2[mf][nf][3] + c1;
        }
    }
    __syncthreads();

    float* red = reinterpret_cast<float*>(smem + ORD);
    if (tid < 192) {
        const int ch = tid % 96, half = tid / 96;
        float m = -1e30f, l = 0.f, a = 0.f;
        for (int t = half * 64; t < half * 64 + 64; t++) {
            if (mk[t] > 0.5f) {
                float x  = Lg[t * 97 + ch];
                float hv = As[t * 97 + ch];
                float n  = fmaxf(m, x);
                float sc = fexp(m - n), w = fexp(x - n);
                l = fmaf(l, sc, w);
                a = fmaf(a, sc, w * hv);
                m = n;
            }
        }
        red[(half * 3 + 0) * 96 + ch] = m;
        red[(half * 3 + 1) * 96 + ch] = l;
        red[(half * 3 + 2) * 96 + ch] = a;
    }
    __syncthreads();
    if (tid < 96) {
        const int ch = tid;
        float m0 = red[0 * 96 + ch], l0 = red[1 * 96 + ch], a0 = red[2 * 96 + ch];
        float m1 = red[3 * 96 + ch], l1 = red[4 * 96 + ch], a1 = red[5 * 96 + ch];
        float n  = fmaxf(fmaxf(m0, m1), -1e30f);
        float s0 = fexp(m0 - n), s1 = fexp(m1 - n);
        float* dst = &g_part[(size_t)mt * 3 * Cq + head * HDq + ch];
        dst[0]      = n;
        dst[Cq]     = l0 * s0 + l1 * s1;
        dst[2 * Cq] = a0 * s0 + a1 * s1;
    }
}

// ---------------------------------------------------------------------------
// K3: merge 4 chunk partials per (batch, channel) -> output
// ---------------------------------------------------------------------------
__global__ __launch_bounds__(256) void k3_reduce(float* __restrict__ out)
{
    const int idx = blockIdx.x * 256 + threadIdx.x;
    const int b = idx / Cq, ch = idx % Cq;

    float m = -1e30f;
    #pragma unroll
    for (int c = 0; c < 4; c++)
        m = fmaxf(m, g_part[(size_t)(b * 4 + c) * 3 * Cq + ch]);

    float l = 0.f, a = 0.f;
    #pragma unroll
    for (int c = 0; c < 4; c++) {
        const float* p = &g_part[(size_t)(b * 4 + c) * 3 * Cq + ch];
        float s = fexp(p[0] - m);
        l = fmaf(p[Cq],     s, l);
        a = fmaf(p[2 * Cq], s, a);
    }
    out[idx] = a / l;
}

// ---------------------------------------------------------------------------
extern "C" void kernel_launch(void* const* d_in, const int* in_sizes, int n_in,
                              void* d_out, int out_size)
{
    const float* X    = (const float*)d_in[0];
    const float* mask = (const float*)d_in[1];
    const float* P    = (const float*)d_in[2];
    const float* bP   = (const float*)d_in[3];
    const float* W1   = (const float*)d_in[4];
    const float* b1   = (const float*)d_in[5];
    const float* W2   = (const float*)d_in[6];
    const float* b2   = (const float*)d_in[7];
    float* out = (float*)d_out;

    cudaFuncSetAttribute(kf_fused, cudaFuncAttributeMaxDynamicSharedMemorySize, KF_SMEM);

    __nv_bfloat16 *Xh, *Xl, *Ph, *Pl, *W1b, *W2b;
    cudaGetSymbolAddress((void**)&Xh,  g_Xh);
    cudaGetSymbolAddress((void**)&Xl,  g_Xl);
    cudaGetSymbolAddress((void**)&Ph,  g_Ph);
    cudaGetSymbolAddress((void**)&Pl,  g_Pl);
    cudaGetSymbolAddress((void**)&W1b, g_W1b);
    cudaGetSymbolAddress((void**)&W2b, g_W2b);

    // K0: bf16 splits / converts
    {
        int n4x = Mq * Dq / 4;
        k0_split<<<(n4x + 255) / 256, 256>>>(X, Xh, Xl, n4x);
        int n4p = Cq * Dq / 4;
        k0_split<<<(n4p + 255) / 256, 256>>>(P, Ph, Pl, n4p);
        int n4w = NHq * HIDq * HDq / 4;
        k0_cvt<<<(n4w + 255) / 256, 256>>>(W1, W1b, n4w);
        k0_cvt<<<(n4w + 255) / 256, 256>>>(W2, W2b, n4w);
    }

    // KF: fused projection + MLP + partial softmax-pool
    dim3 gf(NHq, Mq / 128);
    kf_fused<<<gf, 256, KF_SMEM>>>(Xh, Xl, Ph, Pl, bP, b1, b2, mask);

    // K3: merge partials
    k3_reduce<<<(Bq * Cq) / 256, 256>>>(out);
}